// round 7
// baseline (speedup 1.0000x reference)
#include <cuda_runtime.h>
#include <math.h>
#include <stdint.h>

// ---------------------------------------------------------------------------
// graphNet: 4-layer GCN (21->168->84->42->21) + log_softmax.
// Round-7: software-pipelined CSR gathers (one-group edge-record lookahead
// hides index-fetch latency under gathers), 32-bit gather addressing.
// GEMM = R3/R6 proven scalar-FFMA 8x4 microtile. 4-launch CSR build.
// ---------------------------------------------------------------------------

#define N_MAX 100000
#define E_MAX 1600000
#define F_MAX 168
#define CSR_MAX (E_MAX + 4 * N_MAX)
#define SCAN_B 1024

struct __align__(8) Edge { int src; float w; };

__device__ float g_bufA[(size_t)N_MAX * F_MAX];
__device__ float g_bufB[(size_t)N_MAX * F_MAX];
__device__ int   g_ideg[N_MAX];
__device__ float g_dinv[N_MAX];
__device__ int   g_rowbeg[N_MAX];
__device__ int   g_cur[N_MAX];
__device__ int   g_counter[1];
__device__ Edge  g_csr[CSR_MAX];

// ---------------- init / degree ----------------

__global__ void k_init(int* __restrict__ ideg, int* __restrict__ cur,
                       int* __restrict__ counter, int n) {
    int i = blockIdx.x * blockDim.x + threadIdx.x;
    if (i < n) { ideg[i] = 0; cur[i] = 0; }
    if (i == 0) counter[0] = 0;
}

__global__ void k_count_deg(const int* __restrict__ ei, int* __restrict__ ideg, int E) {
    int e = blockIdx.x * blockDim.x + threadIdx.x;
    if (e < E) atomicAdd(&ideg[ei[E + e]], 1);
}

// ---------------- fused single-pass offsets ----------------

__global__ void k_offsets(const int* __restrict__ ideg, int* __restrict__ row_beg,
                          float* __restrict__ dinv, Edge* __restrict__ csr,
                          int* __restrict__ counter, int n) {
    __shared__ int s[SCAN_B];
    __shared__ int base_sh;
    int i = blockIdx.x * SCAN_B + threadIdx.x;
    int deg = (i < n) ? ideg[i] : 0;
    int pd = (deg + 3) & ~3;
    s[threadIdx.x] = pd;
    __syncthreads();
#pragma unroll
    for (int off = 1; off < SCAN_B; off <<= 1) {
        int t = (threadIdx.x >= off) ? s[threadIdx.x - off] : 0;
        __syncthreads();
        s[threadIdx.x] += t;
        __syncthreads();
    }
    if (threadIdx.x == SCAN_B - 1) base_sh = atomicAdd(counter, s[SCAN_B - 1]);
    __syncthreads();
    int base = base_sh;
    if (i < n) {
        int beg = base + s[threadIdx.x] - pd;
        row_beg[i] = beg;
        dinv[i] = rsqrtf((float)(deg + 1));
        Edge z; z.src = 0; z.w = 0.f;
        for (int p = deg; p < pd; p++) csr[beg + p] = z;
    }
}

// ---------------- CSR scatter ----------------

__global__ void k_scatter(const int* __restrict__ ei, const int* __restrict__ row_beg,
                          int* __restrict__ cur, const float* __restrict__ dinv,
                          Edge* __restrict__ csr, int E) {
    int e = blockIdx.x * blockDim.x + threadIdx.x;
    if (e < E) {
        int s = ei[e];
        int d = ei[E + e];
        int pos = atomicAdd(&cur[d], 1);
        float2 rec = make_float2(__int_as_float(s), dinv[s] * dinv[d]);
        *reinterpret_cast<float2*>(&csr[row_beg[d] + pos]) = rec;
    }
}

// ---------------- vector row load helper ----------------

template <int VW>
__device__ __forceinline__ void ldrow(float (&f)[VW], const float* __restrict__ p) {
    if (VW == 4) { float4 t = *(const float4*)p; f[0]=t.x; f[1]=t.y; f[2]=t.z; f[3]=t.w; }
    else if (VW == 2) { float2 t = *(const float2*)p; f[0]=t.x; f[1]=t.y; }
    else { f[0] = *p; }
}

// ---------------- fused CSR aggregation (software-pipelined) ----------------
// out[v] = [relu]( dinv[v]^2*h[v] + sum_j w_j*h[src_j] [+bias] )
// warp per node; 8-edge groups with one-group lookahead on edge records.

template <int C, int VW, int SIN, int SOUT>
__global__ void k_agg(const float* __restrict__ h, const int* __restrict__ row_beg,
                      const int* __restrict__ ideg,
                      const Edge* __restrict__ csr, const float* __restrict__ dinv,
                      const float* __restrict__ bias, float* __restrict__ out, int n) {
    constexpr int L = C / VW;
    int v = (blockIdx.x * blockDim.x + threadIdx.x) >> 5;
    int lane = threadIdx.x & 31;
    if (v >= n) return;

    if (lane < L) {
        int beg = row_beg[v];
        int endp = beg + ((ideg[v] + 3) & ~3);
        const int off = lane * VW;

        // independent: self-loop row + dinv issued before the edge chain
        float dv = dinv[v];
        float pvv[VW];
        ldrow<VW>(pvv, h + v * SIN + off);

        float acc[VW];
#pragma unroll
        for (int k = 0; k < VW; k++) acc[k] = 0.f;

        int j = beg;
        int4 c0, c1, c2, c3;
        bool have8 = (j + 8 <= endp);
        if (have8) {
            c0 = *(const int4*)(csr + j);
            c1 = *(const int4*)(csr + j + 2);
            c2 = *(const int4*)(csr + j + 4);
            c3 = *(const int4*)(csr + j + 6);
        }
        while (have8) {
            int jn = j + 8;
            bool next8 = (jn + 8 <= endp);
            int4 n0, n1, n2, n3;
            if (next8) {                       // prefetch next group
                n0 = *(const int4*)(csr + jn);
                n1 = *(const int4*)(csr + jn + 2);
                n2 = *(const int4*)(csr + jn + 4);
                n3 = *(const int4*)(csr + jn + 6);
            }
            float f[8][VW];
            ldrow<VW>(f[0], h + c0.x * SIN + off);
            ldrow<VW>(f[1], h + c0.z * SIN + off);
            ldrow<VW>(f[2], h + c1.x * SIN + off);
            ldrow<VW>(f[3], h + c1.z * SIN + off);
            ldrow<VW>(f[4], h + c2.x * SIN + off);
            ldrow<VW>(f[5], h + c2.z * SIN + off);
            ldrow<VW>(f[6], h + c3.x * SIN + off);
            ldrow<VW>(f[7], h + c3.z * SIN + off);
            float w[8];
            w[0] = __int_as_float(c0.y); w[1] = __int_as_float(c0.w);
            w[2] = __int_as_float(c1.y); w[3] = __int_as_float(c1.w);
            w[4] = __int_as_float(c2.y); w[5] = __int_as_float(c2.w);
            w[6] = __int_as_float(c3.y); w[7] = __int_as_float(c3.w);
#pragma unroll
            for (int i = 0; i < 8; i++)
#pragma unroll
                for (int k = 0; k < VW; k++) acc[k] = fmaf(w[i], f[i][k], acc[k]);
            j = jn; have8 = next8;
            c0 = n0; c1 = n1; c2 = n2; c3 = n3;
        }
        if (j < endp) {                        // exactly 4 remain (padded %4)
            int4 e0 = *(const int4*)(csr + j);
            int4 e1 = *(const int4*)(csr + j + 2);
            float f[4][VW];
            ldrow<VW>(f[0], h + e0.x * SIN + off);
            ldrow<VW>(f[1], h + e0.z * SIN + off);
            ldrow<VW>(f[2], h + e1.x * SIN + off);
            ldrow<VW>(f[3], h + e1.z * SIN + off);
            float w[4];
            w[0] = __int_as_float(e0.y); w[1] = __int_as_float(e0.w);
            w[2] = __int_as_float(e1.y); w[3] = __int_as_float(e1.w);
#pragma unroll
            for (int i = 0; i < 4; i++)
#pragma unroll
                for (int k = 0; k < VW; k++) acc[k] = fmaf(w[i], f[i][k], acc[k]);
        }

        float s2 = dv * dv;
        float* po = out + v * SOUT + off;
#pragma unroll
        for (int k = 0; k < VW; k++) {
            float r = fmaf(s2, pvv[k], acc[k]);
            if (bias) r = fmaxf(r + bias[off + k], 0.f);
            po[k] = r;
        }
    } else if (lane * VW < SOUT) {
        float* po = out + v * SOUT + lane * VW;
#pragma unroll
        for (int k = 0; k < VW; k++) po[k] = 0.f;
    }
}

// ---------------- GEMM: C[N x M] = A[N x K] @ W[K x M] (+bias, relu) ----------------
// 256x32 block tile, 8x4 microtile, 256 threads (proven scalar version).

#define GBM 256
#define GBN 32
#define GBK 16

__global__ void __launch_bounds__(256)
k_gemm(const float* __restrict__ A, const float* __restrict__ W,
       const float* __restrict__ bias, float* __restrict__ Cout,
       int N, int K, int M, int SA, int SC, int fuse_bias_relu) {
    __shared__ float As[GBK][GBM];
    __shared__ float Bs[GBK][GBN];

    int tid = threadIdx.x;
    int bm = blockIdx.x * GBM;
    int bn = blockIdx.y * GBN;
    int ty = tid >> 3;
    int tx = tid & 7;
    int row0 = ty * 8;
    int col0 = tx * 4;

    float acc[8][4];
#pragma unroll
    for (int i = 0; i < 8; i++)
#pragma unroll
        for (int j = 0; j < 4; j++) acc[i][j] = 0.f;

    for (int k0 = 0; k0 < K; k0 += GBK) {
#pragma unroll
        for (int i = 0; i < 4; i++) {
            int lin4 = tid + i * 256;
            int r = lin4 >> 2;
            int kk4 = lin4 & 3;
            int gr = bm + r;
            int gk0 = k0 + kk4 * 4;
            float4 a = make_float4(0.f, 0.f, 0.f, 0.f);
            if (gr < N && gk0 + 3 < SA)
                a = *(const float4*)(A + (size_t)gr * SA + gk0);
            As[kk4 * 4 + 0][r] = a.x;
            As[kk4 * 4 + 1][r] = a.y;
            As[kk4 * 4 + 2][r] = a.z;
            As[kk4 * 4 + 3][r] = a.w;
        }
#pragma unroll
        for (int i = 0; i < 2; i++) {
            int lin = tid + i * 256;
            int r = lin >> 5;
            int c = lin & 31;
            int gk = k0 + r, gc = bn + c;
            Bs[r][c] = (gk < K && gc < M) ? W[(size_t)gk * M + gc] : 0.f;
        }
        __syncthreads();

#pragma unroll
        for (int kk = 0; kk < GBK; kk++) {
            float4 a0 = *(const float4*)&As[kk][row0];
            float4 a1 = *(const float4*)&As[kk][row0 + 4];
            float4 b  = *(const float4*)&Bs[kk][col0];
            float av[8] = {a0.x, a0.y, a0.z, a0.w, a1.x, a1.y, a1.z, a1.w};
            float bv[4] = {b.x, b.y, b.z, b.w};
#pragma unroll
            for (int i = 0; i < 8; i++)
#pragma unroll
                for (int j = 0; j < 4; j++) acc[i][j] = fmaf(av[i], bv[j], acc[i][j]);
        }
        __syncthreads();
    }

#pragma unroll
    for (int i = 0; i < 8; i++) {
        int gr = bm + row0 + i;
        if (gr < N) {
#pragma unroll
            for (int j = 0; j < 4; j++) {
                int gc = bn + col0 + j;
                if (gc < M) {
                    float v = acc[i][j];
                    if (fuse_bias_relu) v = fmaxf(v + bias[gc], 0.f);
                    Cout[(size_t)gr * SC + gc] = v;
                }
            }
        }
    }
}

// ---------------- final: pipelined CSR agg + bias + relu + log_softmax ----------------

__global__ void k_final(const float* __restrict__ t4,       // stride 24
                        const int* __restrict__ row_beg,
                        const int* __restrict__ ideg,
                        const Edge* __restrict__ csr,
                        const float* __restrict__ dinv,
                        const float* __restrict__ b4,
                        float* __restrict__ out_z, float* __restrict__ out_pz, int n) {
    int v = (blockIdx.x * blockDim.x + threadIdx.x) >> 5;
    int lane = threadIdx.x & 31;
    if (v >= n) return;

    float val = -INFINITY;
    if (lane < 21) {
        int beg = row_beg[v];
        int endp = beg + ((ideg[v] + 3) & ~3);
        float dv = dinv[v];
        float selfv = t4[v * 24 + lane];
        float acc = 0.f;

        int j = beg;
        int4 c0, c1, c2, c3;
        bool have8 = (j + 8 <= endp);
        if (have8) {
            c0 = *(const int4*)(csr + j);
            c1 = *(const int4*)(csr + j + 2);
            c2 = *(const int4*)(csr + j + 4);
            c3 = *(const int4*)(csr + j + 6);
        }
        while (have8) {
            int jn = j + 8;
            bool next8 = (jn + 8 <= endp);
            int4 n0, n1, n2, n3;
            if (next8) {
                n0 = *(const int4*)(csr + jn);
                n1 = *(const int4*)(csr + jn + 2);
                n2 = *(const int4*)(csr + jn + 4);
                n3 = *(const int4*)(csr + jn + 6);
            }
            float f0 = t4[c0.x * 24 + lane];
            float f1 = t4[c0.z * 24 + lane];
            float f2 = t4[c1.x * 24 + lane];
            float f3 = t4[c1.z * 24 + lane];
            float f4 = t4[c2.x * 24 + lane];
            float f5 = t4[c2.z * 24 + lane];
            float f6 = t4[c3.x * 24 + lane];
            float f7 = t4[c3.z * 24 + lane];
            acc = fmaf(__int_as_float(c0.y), f0, acc);
            acc = fmaf(__int_as_float(c0.w), f1, acc);
            acc = fmaf(__int_as_float(c1.y), f2, acc);
            acc = fmaf(__int_as_float(c1.w), f3, acc);
            acc = fmaf(__int_as_float(c2.y), f4, acc);
            acc = fmaf(__int_as_float(c2.w), f5, acc);
            acc = fmaf(__int_as_float(c3.y), f6, acc);
            acc = fmaf(__int_as_float(c3.w), f7, acc);
            j = jn; have8 = next8;
            c0 = n0; c1 = n1; c2 = n2; c3 = n3;
        }
        if (j < endp) {
            int4 e0 = *(const int4*)(csr + j);
            int4 e1 = *(const int4*)(csr + j + 2);
            float f0 = t4[e0.x * 24 + lane];
            float f1 = t4[e0.z * 24 + lane];
            float f2 = t4[e1.x * 24 + lane];
            float f3 = t4[e1.z * 24 + lane];
            acc = fmaf(__int_as_float(e0.y), f0, acc);
            acc = fmaf(__int_as_float(e0.w), f1, acc);
            acc = fmaf(__int_as_float(e1.y), f2, acc);
            acc = fmaf(__int_as_float(e1.w), f3, acc);
        }
        acc = fmaf(dv * dv, selfv, acc);
        val = fmaxf(acc + b4[lane], 0.f);
    }

    float m = val;
#pragma unroll
    for (int o = 16; o > 0; o >>= 1) m = fmaxf(m, __shfl_xor_sync(0xffffffffu, m, o));
    float ex = (lane < 21) ? __expf(val - m) : 0.f;
    float s = ex;
#pragma unroll
    for (int o = 16; o > 0; o >>= 1) s += __shfl_xor_sync(0xffffffffu, s, o);

    if (lane < 21) {
        out_z[v * 21 + lane] = val;
        out_pz[v * 21 + lane] = val - m - __logf(s);
    }
}

// ---------------------------------------------------------------------------

static inline int cdiv(long long a, int b) { return (int)((a + b - 1) / b); }

extern "C" void kernel_launch(void* const* d_in, const int* in_sizes, int n_in,
                              void* d_out, int out_size) {
    const float* x  = (const float*)d_in[0];
    const int*   ei = (const int*)d_in[1];
    const float* W1 = (const float*)d_in[2];  const float* b1 = (const float*)d_in[3];
    const float* W2 = (const float*)d_in[4];  const float* b2 = (const float*)d_in[5];
    const float* W3 = (const float*)d_in[6];  const float* b3 = (const float*)d_in[7];
    const float* W4 = (const float*)d_in[8];  const float* b4 = (const float*)d_in[9];

    const int n = in_sizes[0] / 21;
    const int E = in_sizes[1] / 2;

    float *bufA, *bufB, *dinv;
    int *ideg, *row_beg, *cur, *counter;
    Edge* csr;
    cudaGetSymbolAddress((void**)&bufA, g_bufA);
    cudaGetSymbolAddress((void**)&bufB, g_bufB);
    cudaGetSymbolAddress((void**)&dinv, g_dinv);
    cudaGetSymbolAddress((void**)&ideg, g_ideg);
    cudaGetSymbolAddress((void**)&row_beg, g_rowbeg);
    cudaGetSymbolAddress((void**)&cur, g_cur);
    cudaGetSymbolAddress((void**)&counter, g_counter);
    cudaGetSymbolAddress((void**)&csr, g_csr);

    float* out_pz = (float*)d_out;
    float* out_z  = (float*)d_out + (size_t)n * 21;

    const int T = 256;
    const int nb = cdiv(n, SCAN_B);

    // --- CSR build (4 launches) ---
    k_init<<<cdiv(n, T), T>>>(ideg, cur, counter, n);
    k_count_deg<<<cdiv(E, T), T>>>(ei, ideg, E);
    k_offsets<<<nb, SCAN_B>>>(ideg, row_beg, dinv, csr, counter, n);
    k_scatter<<<cdiv(E, T), T>>>(ei, row_beg, cur, dinv, csr, E);

    const int aggGrid = cdiv((long long)n * 32, T);

    // --- layer 1: aggregate x (C=21, stride 21 -> 24), GEMM 21->168 (+bias+relu) ---
    k_agg<21, 1, 21, 24><<<aggGrid, T>>>(x, row_beg, ideg, csr, dinv, nullptr, bufA, n);
    {
        dim3 grid(cdiv(n, GBM), cdiv(168, GBN));
        k_gemm<<<grid, T>>>(bufA, W1, b1, bufB, n, 21, 168, 24, 168, 1);
    }
    // --- layer 2: GEMM 168->84, fused agg+bias+relu (C=84, float4) ---
    {
        dim3 grid(cdiv(n, GBM), cdiv(84, GBN));
        k_gemm<<<grid, T>>>(bufB, W2, nullptr, bufA, n, 168, 84, 168, 84, 0);
    }
    k_agg<84, 4, 84, 84><<<aggGrid, T>>>(bufA, row_beg, ideg, csr, dinv, b2, bufB, n);
    // --- layer 3: GEMM 84->42 (out stride 44), agg (C=42, float2) ---
    {
        dim3 grid(cdiv(n, GBM), cdiv(42, GBN));
        k_gemm<<<grid, T>>>(bufB, W3, nullptr, bufA, n, 84, 42, 84, 44, 0);
    }
    k_agg<42, 2, 44, 44><<<aggGrid, T>>>(bufA, row_beg, ideg, csr, dinv, b3, bufB, n);
    // --- layer 4: GEMM 42->21 (out stride 24), fused final ---
    {
        dim3 grid(cdiv(n, GBM), cdiv(21, GBN));
        k_gemm<<<grid, T>>>(bufB, W4, nullptr, bufA, n, 42, 21, 44, 24, 0);
    }
    k_final<<<aggGrid, T>>>(bufA, row_beg, ideg, csr, dinv, b4, out_z, out_pz, n);
}

// round 9
// speedup vs baseline: 1.1149x; 1.1149x over previous
#include <cuda_runtime.h>
#include <math.h>
#include <stdint.h>

// ---------------------------------------------------------------------------
// graphNet: 4-layer GCN (21->168->84->42->21) + log_softmax.
// Round-9 (= R8 resubmit after infra flake): R6 base + straight-line
// unroll-16 edge groups for VW<=2 aggs + final, 2-way ILP CSR-build kernels.
// Layer-2 agg (VW=4) kept at 8-deep.
// ---------------------------------------------------------------------------

#define N_MAX 100000
#define E_MAX 1600000
#define F_MAX 168
#define CSR_MAX (E_MAX + 4 * N_MAX)
#define SCAN_B 1024

struct __align__(8) Edge { int src; float w; };

__device__ float g_bufA[(size_t)N_MAX * F_MAX];
__device__ float g_bufB[(size_t)N_MAX * F_MAX];
__device__ int   g_ideg[N_MAX];
__device__ float g_dinv[N_MAX];
__device__ int   g_rowbeg[N_MAX];
__device__ int   g_cur[N_MAX];
__device__ int   g_counter[1];
__device__ Edge  g_csr[CSR_MAX];

// ---------------- init / degree ----------------

__global__ void k_init(int* __restrict__ ideg, int* __restrict__ cur,
                       int* __restrict__ counter, int n) {
    int i = blockIdx.x * blockDim.x + threadIdx.x;
    if (i < n) { ideg[i] = 0; cur[i] = 0; }
    if (i == 0) counter[0] = 0;
}

// two independent edges per thread (overlapped atomic chains)
__global__ void k_count_deg(const int* __restrict__ ei, int* __restrict__ ideg,
                            int E, int H) {
    int t = blockIdx.x * blockDim.x + threadIdx.x;
    if (t < H) {
        int d0 = ei[E + t];
        int e1 = t + H;
        if (e1 < E) {
            int d1 = ei[E + e1];
            atomicAdd(&ideg[d0], 1);
            atomicAdd(&ideg[d1], 1);
        } else {
            atomicAdd(&ideg[d0], 1);
        }
    }
}

// ---------------- fused single-pass offsets ----------------

__global__ void k_offsets(const int* __restrict__ ideg, int* __restrict__ row_beg,
                          float* __restrict__ dinv, Edge* __restrict__ csr,
                          int* __restrict__ counter, int n) {
    __shared__ int s[SCAN_B];
    __shared__ int base_sh;
    int i = blockIdx.x * SCAN_B + threadIdx.x;
    int deg = (i < n) ? ideg[i] : 0;
    int pd = (deg + 3) & ~3;
    s[threadIdx.x] = pd;
    __syncthreads();
#pragma unroll
    for (int off = 1; off < SCAN_B; off <<= 1) {
        int t = (threadIdx.x >= off) ? s[threadIdx.x - off] : 0;
        __syncthreads();
        s[threadIdx.x] += t;
        __syncthreads();
    }
    if (threadIdx.x == SCAN_B - 1) base_sh = atomicAdd(counter, s[SCAN_B - 1]);
    __syncthreads();
    int base = base_sh;
    if (i < n) {
        int beg = base + s[threadIdx.x] - pd;
        row_beg[i] = beg;
        dinv[i] = rsqrtf((float)(deg + 1));
        Edge z; z.src = 0; z.w = 0.f;
        for (int p = deg; p < pd; p++) csr[beg + p] = z;
    }
}

// ---------------- CSR scatter (two edges per thread) ----------------

__global__ void k_scatter(const int* __restrict__ ei, const int* __restrict__ row_beg,
                          int* __restrict__ cur, const float* __restrict__ dinv,
                          Edge* __restrict__ csr, int E, int H) {
    int t = blockIdx.x * blockDim.x + threadIdx.x;
    if (t >= H) return;
    int e1 = t + H;

    int s0 = ei[t];
    int d0 = ei[E + t];
    int s1 = 0, d1 = 0;
    bool has1 = (e1 < E);
    if (has1) { s1 = ei[e1]; d1 = ei[E + e1]; }

    float w0 = dinv[s0] * dinv[d0];
    int b0 = row_beg[d0];
    float w1 = 0.f; int b1 = 0;
    if (has1) { w1 = dinv[s1] * dinv[d1]; b1 = row_beg[d1]; }

    int p0 = atomicAdd(&cur[d0], 1);
    int p1 = has1 ? atomicAdd(&cur[d1], 1) : 0;

    *reinterpret_cast<float2*>(&csr[b0 + p0]) =
        make_float2(__int_as_float(s0), w0);
    if (has1)
        *reinterpret_cast<float2*>(&csr[b1 + p1]) =
            make_float2(__int_as_float(s1), w1);
}

// ---------------- vector row load helper ----------------

template <int VW>
__device__ __forceinline__ void ldrow(float (&f)[VW], const float* __restrict__ p) {
    if (VW == 4) { float4 t = *(const float4*)p; f[0]=t.x; f[1]=t.y; f[2]=t.z; f[3]=t.w; }
    else if (VW == 2) { float2 t = *(const float2*)p; f[0]=t.x; f[1]=t.y; }
    else { f[0] = *p; }
}

// ---------------- fused CSR aggregation ----------------
// out[v] = [relu]( dinv[v]^2*h[v] + sum_j w_j*h[src_j] [+bias] )
// warp per node; straight-line GRP-edge groups (GRP=16 for VW<=2, 8 for VW=4),
// 4-edge tail loop. All loops are simple counted for-loops (ptxas batches).

template <int C, int VW, int SIN, int SOUT, int GRP>
__global__ void k_agg(const float* __restrict__ h, const int* __restrict__ row_beg,
                      const int* __restrict__ ideg,
                      const Edge* __restrict__ csr, const float* __restrict__ dinv,
                      const float* __restrict__ bias, float* __restrict__ out, int n) {
    constexpr int L = C / VW;
    int v = (blockIdx.x * blockDim.x + threadIdx.x) >> 5;
    int lane = threadIdx.x & 31;
    if (v >= n) return;

    if (lane < L) {
        int beg = row_beg[v];
        int endp = beg + ((ideg[v] + 3) & ~3);
        const int off = lane * VW;

        float dv = dinv[v];
        float pvv[VW];
        ldrow<VW>(pvv, h + v * SIN + off);

        float acc[VW];
#pragma unroll
        for (int k = 0; k < VW; k++) acc[k] = 0.f;

        int j = beg;
        for (; j + GRP <= endp; j += GRP) {
            int4 e[GRP / 2];
#pragma unroll
            for (int i = 0; i < GRP / 2; i++) e[i] = *(const int4*)(csr + j + 2 * i);
            float f[GRP][VW];
#pragma unroll
            for (int i = 0; i < GRP / 2; i++) {
                ldrow<VW>(f[2 * i + 0], h + e[i].x * SIN + off);
                ldrow<VW>(f[2 * i + 1], h + e[i].z * SIN + off);
            }
#pragma unroll
            for (int i = 0; i < GRP / 2; i++) {
                float w0 = __int_as_float(e[i].y);
                float w1 = __int_as_float(e[i].w);
#pragma unroll
                for (int k = 0; k < VW; k++) {
                    acc[k] = fmaf(w0, f[2 * i + 0][k], acc[k]);
                    acc[k] = fmaf(w1, f[2 * i + 1][k], acc[k]);
                }
            }
        }
        for (; j + 4 <= endp; j += 4) {      // padded deg %4 == 0
            int4 e0 = *(const int4*)(csr + j);
            int4 e1 = *(const int4*)(csr + j + 2);
            float f[4][VW];
            ldrow<VW>(f[0], h + e0.x * SIN + off);
            ldrow<VW>(f[1], h + e0.z * SIN + off);
            ldrow<VW>(f[2], h + e1.x * SIN + off);
            ldrow<VW>(f[3], h + e1.z * SIN + off);
            float w[4];
            w[0] = __int_as_float(e0.y); w[1] = __int_as_float(e0.w);
            w[2] = __int_as_float(e1.y); w[3] = __int_as_float(e1.w);
#pragma unroll
            for (int i = 0; i < 4; i++)
#pragma unroll
                for (int k = 0; k < VW; k++) acc[k] = fmaf(w[i], f[i][k], acc[k]);
        }

        float s2 = dv * dv;
        float* po = out + v * SOUT + off;
#pragma unroll
        for (int k = 0; k < VW; k++) {
            float r = fmaf(s2, pvv[k], acc[k]);
            if (bias) r = fmaxf(r + bias[off + k], 0.f);
            po[k] = r;
        }
    } else if (lane * VW < SOUT) {
        float* po = out + v * SOUT + lane * VW;
#pragma unroll
        for (int k = 0; k < VW; k++) po[k] = 0.f;
    }
}

// ---------------- GEMM: C[N x M] = A[N x K] @ W[K x M] (+bias, relu) ----------------
// 256x32 block tile, 8x4 microtile, 256 threads (proven scalar version).

#define GBM 256
#define GBN 32
#define GBK 16

__global__ void __launch_bounds__(256)
k_gemm(const float* __restrict__ A, const float* __restrict__ W,
       const float* __restrict__ bias, float* __restrict__ Cout,
       int N, int K, int M, int SA, int SC, int fuse_bias_relu) {
    __shared__ float As[GBK][GBM];
    __shared__ float Bs[GBK][GBN];

    int tid = threadIdx.x;
    int bm = blockIdx.x * GBM;
    int bn = blockIdx.y * GBN;
    int ty = tid >> 3;
    int tx = tid & 7;
    int row0 = ty * 8;
    int col0 = tx * 4;

    float acc[8][4];
#pragma unroll
    for (int i = 0; i < 8; i++)
#pragma unroll
        for (int j = 0; j < 4; j++) acc[i][j] = 0.f;

    for (int k0 = 0; k0 < K; k0 += GBK) {
#pragma unroll
        for (int i = 0; i < 4; i++) {
            int lin4 = tid + i * 256;
            int r = lin4 >> 2;
            int kk4 = lin4 & 3;
            int gr = bm + r;
            int gk0 = k0 + kk4 * 4;
            float4 a = make_float4(0.f, 0.f, 0.f, 0.f);
            if (gr < N && gk0 + 3 < SA)
                a = *(const float4*)(A + (size_t)gr * SA + gk0);
            As[kk4 * 4 + 0][r] = a.x;
            As[kk4 * 4 + 1][r] = a.y;
            As[kk4 * 4 + 2][r] = a.z;
            As[kk4 * 4 + 3][r] = a.w;
        }
#pragma unroll
        for (int i = 0; i < 2; i++) {
            int lin = tid + i * 256;
            int r = lin >> 5;
            int c = lin & 31;
            int gk = k0 + r, gc = bn + c;
            Bs[r][c] = (gk < K && gc < M) ? W[(size_t)gk * M + gc] : 0.f;
        }
        __syncthreads();

#pragma unroll
        for (int kk = 0; kk < GBK; kk++) {
            float4 a0 = *(const float4*)&As[kk][row0];
            float4 a1 = *(const float4*)&As[kk][row0 + 4];
            float4 b  = *(const float4*)&Bs[kk][col0];
            float av[8] = {a0.x, a0.y, a0.z, a0.w, a1.x, a1.y, a1.z, a1.w};
            float bv[4] = {b.x, b.y, b.z, b.w};
#pragma unroll
            for (int i = 0; i < 8; i++)
#pragma unroll
                for (int j = 0; j < 4; j++) acc[i][j] = fmaf(av[i], bv[j], acc[i][j]);
        }
        __syncthreads();
    }

#pragma unroll
    for (int i = 0; i < 8; i++) {
        int gr = bm + row0 + i;
        if (gr < N) {
#pragma unroll
            for (int j = 0; j < 4; j++) {
                int gc = bn + col0 + j;
                if (gc < M) {
                    float v = acc[i][j];
                    if (fuse_bias_relu) v = fmaxf(v + bias[gc], 0.f);
                    Cout[(size_t)gr * SC + gc] = v;
                }
            }
        }
    }
}

// ---------------- final: CSR agg + bias + relu + log_softmax ----------------

__global__ void k_final(const float* __restrict__ t4,       // stride 24
                        const int* __restrict__ row_beg,
                        const int* __restrict__ ideg,
                        const Edge* __restrict__ csr,
                        const float* __restrict__ dinv,
                        const float* __restrict__ b4,
                        float* __restrict__ out_z, float* __restrict__ out_pz, int n) {
    int v = (blockIdx.x * blockDim.x + threadIdx.x) >> 5;
    int lane = threadIdx.x & 31;
    if (v >= n) return;

    float val = -INFINITY;
    if (lane < 21) {
        int beg = row_beg[v];
        int endp = beg + ((ideg[v] + 3) & ~3);
        float dv = dinv[v];
        float selfv = t4[v * 24 + lane];
        float acc = 0.f;

        int j = beg;
        for (; j + 16 <= endp; j += 16) {
            int4 e[8];
#pragma unroll
            for (int i = 0; i < 8; i++) e[i] = *(const int4*)(csr + j + 2 * i);
            float f[16];
#pragma unroll
            for (int i = 0; i < 8; i++) {
                f[2 * i + 0] = t4[e[i].x * 24 + lane];
                f[2 * i + 1] = t4[e[i].z * 24 + lane];
            }
#pragma unroll
            for (int i = 0; i < 8; i++) {
                acc = fmaf(__int_as_float(e[i].y), f[2 * i + 0], acc);
                acc = fmaf(__int_as_float(e[i].w), f[2 * i + 1], acc);
            }
        }
        for (; j + 4 <= endp; j += 4) {
            int4 e0 = *(const int4*)(csr + j);
            int4 e1 = *(const int4*)(csr + j + 2);
            float f0 = t4[e0.x * 24 + lane];
            float f1 = t4[e0.z * 24 + lane];
            float f2 = t4[e1.x * 24 + lane];
            float f3 = t4[e1.z * 24 + lane];
            acc = fmaf(__int_as_float(e0.y), f0, acc);
            acc = fmaf(__int_as_float(e0.w), f1, acc);
            acc = fmaf(__int_as_float(e1.y), f2, acc);
            acc = fmaf(__int_as_float(e1.w), f3, acc);
        }
        acc = fmaf(dv * dv, selfv, acc);
        val = fmaxf(acc + b4[lane], 0.f);
    }

    float m = val;
#pragma unroll
    for (int o = 16; o > 0; o >>= 1) m = fmaxf(m, __shfl_xor_sync(0xffffffffu, m, o));
    float ex = (lane < 21) ? __expf(val - m) : 0.f;
    float s = ex;
#pragma unroll
    for (int o = 16; o > 0; o >>= 1) s += __shfl_xor_sync(0xffffffffu, s, o);

    if (lane < 21) {
        out_z[v * 21 + lane] = val;
        out_pz[v * 21 + lane] = val - m - __logf(s);
    }
}

// ---------------------------------------------------------------------------

static inline int cdiv(long long a, int b) { return (int)((a + b - 1) / b); }

extern "C" void kernel_launch(void* const* d_in, const int* in_sizes, int n_in,
                              void* d_out, int out_size) {
    const float* x  = (const float*)d_in[0];
    const int*   ei = (const int*)d_in[1];
    const float* W1 = (const float*)d_in[2];  const float* b1 = (const float*)d_in[3];
    const float* W2 = (const float*)d_in[4];  const float* b2 = (const float*)d_in[5];
    const float* W3 = (const float*)d_in[6];  const float* b3 = (const float*)d_in[7];
    const float* W4 = (const float*)d_in[8];  const float* b4 = (const float*)d_in[9];

    const int n = in_sizes[0] / 21;
    const int E = in_sizes[1] / 2;
    const int H = (E + 1) / 2;

    float *bufA, *bufB, *dinv;
    int *ideg, *row_beg, *cur, *counter;
    Edge* csr;
    cudaGetSymbolAddress((void**)&bufA, g_bufA);
    cudaGetSymbolAddress((void**)&bufB, g_bufB);
    cudaGetSymbolAddress((void**)&dinv, g_dinv);
    cudaGetSymbolAddress((void**)&ideg, g_ideg);
    cudaGetSymbolAddress((void**)&row_beg, g_rowbeg);
    cudaGetSymbolAddress((void**)&cur, g_cur);
    cudaGetSymbolAddress((void**)&counter, g_counter);
    cudaGetSymbolAddress((void**)&csr, g_csr);

    float* out_pz = (float*)d_out;
    float* out_z  = (float*)d_out + (size_t)n * 21;

    const int T = 256;
    const int nb = cdiv(n, SCAN_B);

    // --- CSR build (4 launches) ---
    k_init<<<cdiv(n, T), T>>>(ideg, cur, counter, n);
    k_count_deg<<<cdiv(H, T), T>>>(ei, ideg, E, H);
    k_offsets<<<nb, SCAN_B>>>(ideg, row_beg, dinv, csr, counter, n);
    k_scatter<<<cdiv(H, T), T>>>(ei, row_beg, cur, dinv, csr, E, H);

    const int aggGrid = cdiv((long long)n * 32, T);

    // --- layer 1: aggregate x (C=21, stride 21 -> 24), GEMM 21->168 (+bias+relu) ---
    k_agg<21, 1, 21, 24, 16><<<aggGrid, T>>>(x, row_beg, ideg, csr, dinv, nullptr, bufA, n);
    {
        dim3 grid(cdiv(n, GBM), cdiv(168, GBN));
        k_gemm<<<grid, T>>>(bufA, W1, b1, bufB, n, 21, 168, 24, 168, 1);
    }
    // --- layer 2: GEMM 168->84, fused agg+bias+relu (C=84, float4, 8-deep) ---
    {
        dim3 grid(cdiv(n, GBM), cdiv(84, GBN));
        k_gemm<<<grid, T>>>(bufB, W2, nullptr, bufA, n, 168, 84, 168, 84, 0);
    }
    k_agg<84, 4, 84, 84, 8><<<aggGrid, T>>>(bufA, row_beg, ideg, csr, dinv, b2, bufB, n);
    // --- layer 3: GEMM 84->42 (out stride 44), agg (C=42, float2, 16-deep) ---
    {
        dim3 grid(cdiv(n, GBM), cdiv(42, GBN));
        k_gemm<<<grid, T>>>(bufB, W3, nullptr, bufA, n, 84, 42, 84, 44, 0);
    }
    k_agg<42, 2, 44, 44, 16><<<aggGrid, T>>>(bufA, row_beg, ideg, csr, dinv, b3, bufB, n);
    // --- layer 4: GEMM 42->21 (out stride 24), fused final ---
    {
        dim3 grid(cdiv(n, GBM), cdiv(21, GBN));
        k_gemm<<<grid, T>>>(bufB, W4, nullptr, bufA, n, 42, 21, 44, 24, 0);
    }
    k_final<<<aggGrid, T>>>(bufA, row_beg, ideg, csr, dinv, b4, out_z, out_pz, n);
}

// round 10
// speedup vs baseline: 1.1748x; 1.0537x over previous
#include <cuda_runtime.h>
#include <math.h>
#include <stdint.h>

// ---------------------------------------------------------------------------
// graphNet: 4-layer GCN (21->168->84->42->21) + log_softmax.
// Round-10: R6 base (best 462.8us) + DENSE agg thread mapping: thread per
// (node, channel-group), TPN=SOUT/VW threads/node instead of a 32-lane warp
// with 11 idle lanes. No shuffles needed in k_agg (lanes independent).
// GRP=8 edge groups (measured-best), simple 1-edge CSR-build kernels.
// ---------------------------------------------------------------------------

#define N_MAX 100000
#define E_MAX 1600000
#define F_MAX 168
#define CSR_MAX (E_MAX + 4 * N_MAX)
#define SCAN_B 1024

struct __align__(8) Edge { int src; float w; };

__device__ float g_bufA[(size_t)N_MAX * F_MAX];
__device__ float g_bufB[(size_t)N_MAX * F_MAX];
__device__ int   g_ideg[N_MAX];
__device__ float g_dinv[N_MAX];
__device__ int   g_rowbeg[N_MAX];
__device__ int   g_cur[N_MAX];
__device__ int   g_counter[1];
__device__ Edge  g_csr[CSR_MAX];

// ---------------- init / degree ----------------

__global__ void k_init(int* __restrict__ ideg, int* __restrict__ cur,
                       int* __restrict__ counter, int n) {
    int i = blockIdx.x * blockDim.x + threadIdx.x;
    if (i < n) { ideg[i] = 0; cur[i] = 0; }
    if (i == 0) counter[0] = 0;
}

__global__ void k_count_deg(const int* __restrict__ ei, int* __restrict__ ideg, int E) {
    int e = blockIdx.x * blockDim.x + threadIdx.x;
    if (e < E) atomicAdd(&ideg[ei[E + e]], 1);
}

// ---------------- fused single-pass offsets ----------------

__global__ void k_offsets(const int* __restrict__ ideg, int* __restrict__ row_beg,
                          float* __restrict__ dinv, Edge* __restrict__ csr,
                          int* __restrict__ counter, int n) {
    __shared__ int s[SCAN_B];
    __shared__ int base_sh;
    int i = blockIdx.x * SCAN_B + threadIdx.x;
    int deg = (i < n) ? ideg[i] : 0;
    int pd = (deg + 3) & ~3;
    s[threadIdx.x] = pd;
    __syncthreads();
#pragma unroll
    for (int off = 1; off < SCAN_B; off <<= 1) {
        int t = (threadIdx.x >= off) ? s[threadIdx.x - off] : 0;
        __syncthreads();
        s[threadIdx.x] += t;
        __syncthreads();
    }
    if (threadIdx.x == SCAN_B - 1) base_sh = atomicAdd(counter, s[SCAN_B - 1]);
    __syncthreads();
    int base = base_sh;
    if (i < n) {
        int beg = base + s[threadIdx.x] - pd;
        row_beg[i] = beg;
        dinv[i] = rsqrtf((float)(deg + 1));
        Edge z; z.src = 0; z.w = 0.f;
        for (int p = deg; p < pd; p++) csr[beg + p] = z;
    }
}

// ---------------- CSR scatter ----------------

__global__ void k_scatter(const int* __restrict__ ei, const int* __restrict__ row_beg,
                          int* __restrict__ cur, const float* __restrict__ dinv,
                          Edge* __restrict__ csr, int E) {
    int e = blockIdx.x * blockDim.x + threadIdx.x;
    if (e < E) {
        int s = ei[e];
        int d = ei[E + e];
        int pos = atomicAdd(&cur[d], 1);
        float2 rec = make_float2(__int_as_float(s), dinv[s] * dinv[d]);
        *reinterpret_cast<float2*>(&csr[row_beg[d] + pos]) = rec;
    }
}

// ---------------- vector row load helper ----------------

template <int VW>
__device__ __forceinline__ void ldrow(float (&f)[VW], const float* __restrict__ p) {
    if (VW == 4) { float4 t = *(const float4*)p; f[0]=t.x; f[1]=t.y; f[2]=t.z; f[3]=t.w; }
    else if (VW == 2) { float2 t = *(const float2*)p; f[0]=t.x; f[1]=t.y; }
    else { f[0] = *p; }
}

// ---------------- fused CSR aggregation (dense thread mapping) ----------------
// out[v] = [relu]( dinv[v]^2*h[v] + sum_j w_j*h[src_j] [+bias] )
// thread per (node, channel-group): TPN = SOUT/VW threads per node;
// groups r < L compute, groups L..TPN-1 zero the pad columns.
// Threads are fully independent (no warp collectives).

template <int C, int VW, int SIN, int SOUT>
__global__ void k_agg(const float* __restrict__ h, const int* __restrict__ row_beg,
                      const int* __restrict__ ideg,
                      const Edge* __restrict__ csr, const float* __restrict__ dinv,
                      const float* __restrict__ bias, float* __restrict__ out, int n) {
    constexpr int L = C / VW;
    constexpr int TPN = SOUT / VW;
    int t = blockIdx.x * blockDim.x + threadIdx.x;
    int v = t / TPN;
    int r = t - v * TPN;
    if (v >= n) return;

    if (r < L) {
        int beg = row_beg[v];
        int endp = beg + ((ideg[v] + 3) & ~3);
        const int off = r * VW;

        float dv = dinv[v];
        float pvv[VW];
        ldrow<VW>(pvv, h + v * SIN + off);

        float acc[VW];
#pragma unroll
        for (int k = 0; k < VW; k++) acc[k] = 0.f;

        int j = beg;
        for (; j + 8 <= endp; j += 8) {
            int4 e0 = *(const int4*)(csr + j);
            int4 e1 = *(const int4*)(csr + j + 2);
            int4 e2 = *(const int4*)(csr + j + 4);
            int4 e3 = *(const int4*)(csr + j + 6);
            float f[8][VW];
            ldrow<VW>(f[0], h + e0.x * SIN + off);
            ldrow<VW>(f[1], h + e0.z * SIN + off);
            ldrow<VW>(f[2], h + e1.x * SIN + off);
            ldrow<VW>(f[3], h + e1.z * SIN + off);
            ldrow<VW>(f[4], h + e2.x * SIN + off);
            ldrow<VW>(f[5], h + e2.z * SIN + off);
            ldrow<VW>(f[6], h + e3.x * SIN + off);
            ldrow<VW>(f[7], h + e3.z * SIN + off);
            float w[8];
            w[0] = __int_as_float(e0.y); w[1] = __int_as_float(e0.w);
            w[2] = __int_as_float(e1.y); w[3] = __int_as_float(e1.w);
            w[4] = __int_as_float(e2.y); w[5] = __int_as_float(e2.w);
            w[6] = __int_as_float(e3.y); w[7] = __int_as_float(e3.w);
#pragma unroll
            for (int i = 0; i < 8; i++)
#pragma unroll
                for (int k = 0; k < VW; k++) acc[k] = fmaf(w[i], f[i][k], acc[k]);
        }
        if (j < endp) {                        // exactly 4 remain (padded %4)
            int4 e0 = *(const int4*)(csr + j);
            int4 e1 = *(const int4*)(csr + j + 2);
            float f[4][VW];
            ldrow<VW>(f[0], h + e0.x * SIN + off);
            ldrow<VW>(f[1], h + e0.z * SIN + off);
            ldrow<VW>(f[2], h + e1.x * SIN + off);
            ldrow<VW>(f[3], h + e1.z * SIN + off);
            float w[4];
            w[0] = __int_as_float(e0.y); w[1] = __int_as_float(e0.w);
            w[2] = __int_as_float(e1.y); w[3] = __int_as_float(e1.w);
#pragma unroll
            for (int i = 0; i < 4; i++)
#pragma unroll
                for (int k = 0; k < VW; k++) acc[k] = fmaf(w[i], f[i][k], acc[k]);
        }

        float s2 = dv * dv;
        float* po = out + v * SOUT + off;
#pragma unroll
        for (int k = 0; k < VW; k++) {
            float r2 = fmaf(s2, pvv[k], acc[k]);
            if (bias) r2 = fmaxf(r2 + bias[off + k], 0.f);
            po[k] = r2;
        }
    } else {
        // pad-column zero fill
        float* po = out + v * SOUT + r * VW;
#pragma unroll
        for (int k = 0; k < VW; k++) po[k] = 0.f;
    }
}

// ---------------- GEMM: C[N x M] = A[N x K] @ W[K x M] (+bias, relu) ----------------
// 256x32 block tile, 8x4 microtile, 256 threads (proven scalar version).

#define GBM 256
#define GBN 32
#define GBK 16

__global__ void __launch_bounds__(256)
k_gemm(const float* __restrict__ A, const float* __restrict__ W,
       const float* __restrict__ bias, float* __restrict__ Cout,
       int N, int K, int M, int SA, int SC, int fuse_bias_relu) {
    __shared__ float As[GBK][GBM];
    __shared__ float Bs[GBK][GBN];

    int tid = threadIdx.x;
    int bm = blockIdx.x * GBM;
    int bn = blockIdx.y * GBN;
    int ty = tid >> 3;
    int tx = tid & 7;
    int row0 = ty * 8;
    int col0 = tx * 4;

    float acc[8][4];
#pragma unroll
    for (int i = 0; i < 8; i++)
#pragma unroll
        for (int j = 0; j < 4; j++) acc[i][j] = 0.f;

    for (int k0 = 0; k0 < K; k0 += GBK) {
#pragma unroll
        for (int i = 0; i < 4; i++) {
            int lin4 = tid + i * 256;
            int r = lin4 >> 2;
            int kk4 = lin4 & 3;
            int gr = bm + r;
            int gk0 = k0 + kk4 * 4;
            float4 a = make_float4(0.f, 0.f, 0.f, 0.f);
            if (gr < N && gk0 + 3 < SA)
                a = *(const float4*)(A + (size_t)gr * SA + gk0);
            As[kk4 * 4 + 0][r] = a.x;
            As[kk4 * 4 + 1][r] = a.y;
            As[kk4 * 4 + 2][r] = a.z;
            As[kk4 * 4 + 3][r] = a.w;
        }
#pragma unroll
        for (int i = 0; i < 2; i++) {
            int lin = tid + i * 256;
            int r = lin >> 5;
            int c = lin & 31;
            int gk = k0 + r, gc = bn + c;
            Bs[r][c] = (gk < K && gc < M) ? W[(size_t)gk * M + gc] : 0.f;
        }
        __syncthreads();

#pragma unroll
        for (int kk = 0; kk < GBK; kk++) {
            float4 a0 = *(const float4*)&As[kk][row0];
            float4 a1 = *(const float4*)&As[kk][row0 + 4];
            float4 b  = *(const float4*)&Bs[kk][col0];
            float av[8] = {a0.x, a0.y, a0.z, a0.w, a1.x, a1.y, a1.z, a1.w};
            float bv[4] = {b.x, b.y, b.z, b.w};
#pragma unroll
            for (int i = 0; i < 8; i++)
#pragma unroll
                for (int j = 0; j < 4; j++) acc[i][j] = fmaf(av[i], bv[j], acc[i][j]);
        }
        __syncthreads();
    }

#pragma unroll
    for (int i = 0; i < 8; i++) {
        int gr = bm + row0 + i;
        if (gr < N) {
#pragma unroll
            for (int j = 0; j < 4; j++) {
                int gc = bn + col0 + j;
                if (gc < M) {
                    float v = acc[i][j];
                    if (fuse_bias_relu) v = fmaxf(v + bias[gc], 0.f);
                    Cout[(size_t)gr * SC + gc] = v;
                }
            }
        }
    }
}

// ---------------- final: CSR agg + bias + relu + log_softmax (warp/node) --------

__global__ void k_final(const float* __restrict__ t4,       // stride 24
                        const int* __restrict__ row_beg,
                        const int* __restrict__ ideg,
                        const Edge* __restrict__ csr,
                        const float* __restrict__ dinv,
                        const float* __restrict__ b4,
                        float* __restrict__ out_z, float* __restrict__ out_pz, int n) {
    int v = (blockIdx.x * blockDim.x + threadIdx.x) >> 5;
    int lane = threadIdx.x & 31;
    if (v >= n) return;

    float val = -INFINITY;
    if (lane < 21) {
        int beg = row_beg[v];
        int endp = beg + ((ideg[v] + 3) & ~3);
        float dv = dinv[v];
        float selfv = t4[v * 24 + lane];
        float acc = 0.f;

        int j = beg;
        for (; j + 8 <= endp; j += 8) {
            int4 e0 = *(const int4*)(csr + j);
            int4 e1 = *(const int4*)(csr + j + 2);
            int4 e2 = *(const int4*)(csr + j + 4);
            int4 e3 = *(const int4*)(csr + j + 6);
            float f0 = t4[e0.x * 24 + lane];
            float f1 = t4[e0.z * 24 + lane];
            float f2 = t4[e1.x * 24 + lane];
            float f3 = t4[e1.z * 24 + lane];
            float f4 = t4[e2.x * 24 + lane];
            float f5 = t4[e2.z * 24 + lane];
            float f6 = t4[e3.x * 24 + lane];
            float f7 = t4[e3.z * 24 + lane];
            acc = fmaf(__int_as_float(e0.y), f0, acc);
            acc = fmaf(__int_as_float(e0.w), f1, acc);
            acc = fmaf(__int_as_float(e1.y), f2, acc);
            acc = fmaf(__int_as_float(e1.w), f3, acc);
            acc = fmaf(__int_as_float(e2.y), f4, acc);
            acc = fmaf(__int_as_float(e2.w), f5, acc);
            acc = fmaf(__int_as_float(e3.y), f6, acc);
            acc = fmaf(__int_as_float(e3.w), f7, acc);
        }
        if (j < endp) {
            int4 e0 = *(const int4*)(csr + j);
            int4 e1 = *(const int4*)(csr + j + 2);
            float f0 = t4[e0.x * 24 + lane];
            float f1 = t4[e0.z * 24 + lane];
            float f2 = t4[e1.x * 24 + lane];
            float f3 = t4[e1.z * 24 + lane];
            acc = fmaf(__int_as_float(e0.y), f0, acc);
            acc = fmaf(__int_as_float(e0.w), f1, acc);
            acc = fmaf(__int_as_float(e1.y), f2, acc);
            acc = fmaf(__int_as_float(e1.w), f3, acc);
        }
        acc = fmaf(dv * dv, selfv, acc);
        val = fmaxf(acc + b4[lane], 0.f);
    }

    float m = val;
#pragma unroll
    for (int o = 16; o > 0; o >>= 1) m = fmaxf(m, __shfl_xor_sync(0xffffffffu, m, o));
    float ex = (lane < 21) ? __expf(val - m) : 0.f;
    float s = ex;
#pragma unroll
    for (int o = 16; o > 0; o >>= 1) s += __shfl_xor_sync(0xffffffffu, s, o);

    if (lane < 21) {
        out_z[v * 21 + lane] = val;
        out_pz[v * 21 + lane] = val - m - __logf(s);
    }
}

// ---------------------------------------------------------------------------

static inline int cdiv(long long a, int b) { return (int)((a + b - 1) / b); }

extern "C" void kernel_launch(void* const* d_in, const int* in_sizes, int n_in,
                              void* d_out, int out_size) {
    const float* x  = (const float*)d_in[0];
    const int*   ei = (const int*)d_in[1];
    const float* W1 = (const float*)d_in[2];  const float* b1 = (const float*)d_in[3];
    const float* W2 = (const float*)d_in[4];  const float* b2 = (const float*)d_in[5];
    const float* W3 = (const float*)d_in[6];  const float* b3 = (const float*)d_in[7];
    const float* W4 = (const float*)d_in[8];  const float* b4 = (const float*)d_in[9];

    const int n = in_sizes[0] / 21;
    const int E = in_sizes[1] / 2;

    float *bufA, *bufB, *dinv;
    int *ideg, *row_beg, *cur, *counter;
    Edge* csr;
    cudaGetSymbolAddress((void**)&bufA, g_bufA);
    cudaGetSymbolAddress((void**)&bufB, g_bufB);
    cudaGetSymbolAddress((void**)&dinv, g_dinv);
    cudaGetSymbolAddress((void**)&ideg, g_ideg);
    cudaGetSymbolAddress((void**)&row_beg, g_rowbeg);
    cudaGetSymbolAddress((void**)&cur, g_cur);
    cudaGetSymbolAddress((void**)&counter, g_counter);
    cudaGetSymbolAddress((void**)&csr, g_csr);

    float* out_pz = (float*)d_out;
    float* out_z  = (float*)d_out + (size_t)n * 21;

    const int T = 256;
    const int nb = cdiv(n, SCAN_B);

    // --- CSR build (4 launches) ---
    k_init<<<cdiv(n, T), T>>>(ideg, cur, counter, n);
    k_count_deg<<<cdiv(E, T), T>>>(ei, ideg, E);
    k_offsets<<<nb, SCAN_B>>>(ideg, row_beg, dinv, csr, counter, n);
    k_scatter<<<cdiv(E, T), T>>>(ei, row_beg, cur, dinv, csr, E);

    // --- layer 1: dense agg of x (C=21, TPN=24), GEMM 21->168 (+bias+relu) ---
    k_agg<21, 1, 21, 24><<<cdiv((long long)n * 24, T), T>>>(
        x, row_beg, ideg, csr, dinv, nullptr, bufA, n);
    {
        dim3 grid(cdiv(n, GBM), cdiv(168, GBN));
        k_gemm<<<grid, T>>>(bufA, W1, b1, bufB, n, 21, 168, 24, 168, 1);
    }
    // --- layer 2: GEMM 168->84, dense agg+bias+relu (C=84, VW=4, TPN=21) ---
    {
        dim3 grid(cdiv(n, GBM), cdiv(84, GBN));
        k_gemm<<<grid, T>>>(bufB, W2, nullptr, bufA, n, 168, 84, 168, 84, 0);
    }
    k_agg<84, 4, 84, 84><<<cdiv((long long)n * 21, T), T>>>(
        bufA, row_beg, ideg, csr, dinv, b2, bufB, n);
    // --- layer 3: GEMM 84->42 (out stride 44), dense agg (C=42, VW=2, TPN=22) ---
    {
        dim3 grid(cdiv(n, GBM), cdiv(42, GBN));
        k_gemm<<<grid, T>>>(bufB, W3, nullptr, bufA, n, 84, 42, 84, 44, 0);
    }
    k_agg<42, 2, 44, 44><<<cdiv((long long)n * 22, T), T>>>(
        bufA, row_beg, ideg, csr, dinv, b3, bufB, n);
    // --- layer 4: GEMM 42->21 (out stride 24), fused final ---
    {
        dim3 grid(cdiv(n, GBM), cdiv(21, GBN));
        k_gemm<<<grid, T>>>(bufB, W4, nullptr, bufA, n, 42, 21, 44, 24, 0);
    }
    k_final<<<cdiv((long long)n * 32, T), T>>>(
        bufA, row_beg, ideg, csr, dinv, b4, out_z, out_pz, n);
}

// round 11
// speedup vs baseline: 1.3402x; 1.1408x over previous
#include <cuda_runtime.h>
#include <math.h>
#include <stdint.h>

// ---------------------------------------------------------------------------
// graphNet: 4-layer GCN (21->168->84->42->21) + log_softmax.
// Round-11: R10 base (best 453.2us) + tf32 tensor-core GEMM (mma.m16n8k8)
// for the two largest GEMMs (layers 2, 3). Layers 1/4 stay exact fp32.
// Dense agg mapping, GRP=8 gather groups, 4-launch CSR build.
// ---------------------------------------------------------------------------

#define N_MAX 100000
#define E_MAX 1600000
#define F_MAX 168
#define CSR_MAX (E_MAX + 4 * N_MAX)
#define SCAN_B 1024

struct __align__(8) Edge { int src; float w; };

__device__ float g_bufA[(size_t)N_MAX * F_MAX];
__device__ float g_bufB[(size_t)N_MAX * F_MAX];
__device__ int   g_ideg[N_MAX];
__device__ float g_dinv[N_MAX];
__device__ int   g_rowbeg[N_MAX];
__device__ int   g_cur[N_MAX];
__device__ int   g_counter[1];
__device__ Edge  g_csr[CSR_MAX];

// ---------------- init / degree ----------------

__global__ void k_init(int* __restrict__ ideg, int* __restrict__ cur,
                       int* __restrict__ counter, int n) {
    int i = blockIdx.x * blockDim.x + threadIdx.x;
    if (i < n) { ideg[i] = 0; cur[i] = 0; }
    if (i == 0) counter[0] = 0;
}

__global__ void k_count_deg(const int* __restrict__ ei, int* __restrict__ ideg, int E) {
    int e = blockIdx.x * blockDim.x + threadIdx.x;
    if (e < E) atomicAdd(&ideg[ei[E + e]], 1);
}

// ---------------- fused single-pass offsets ----------------

__global__ void k_offsets(const int* __restrict__ ideg, int* __restrict__ row_beg,
                          float* __restrict__ dinv, Edge* __restrict__ csr,
                          int* __restrict__ counter, int n) {
    __shared__ int s[SCAN_B];
    __shared__ int base_sh;
    int i = blockIdx.x * SCAN_B + threadIdx.x;
    int deg = (i < n) ? ideg[i] : 0;
    int pd = (deg + 3) & ~3;
    s[threadIdx.x] = pd;
    __syncthreads();
#pragma unroll
    for (int off = 1; off < SCAN_B; off <<= 1) {
        int t = (threadIdx.x >= off) ? s[threadIdx.x - off] : 0;
        __syncthreads();
        s[threadIdx.x] += t;
        __syncthreads();
    }
    if (threadIdx.x == SCAN_B - 1) base_sh = atomicAdd(counter, s[SCAN_B - 1]);
    __syncthreads();
    int base = base_sh;
    if (i < n) {
        int beg = base + s[threadIdx.x] - pd;
        row_beg[i] = beg;
        dinv[i] = rsqrtf((float)(deg + 1));
        Edge z; z.src = 0; z.w = 0.f;
        for (int p = deg; p < pd; p++) csr[beg + p] = z;
    }
}

// ---------------- CSR scatter ----------------

__global__ void k_scatter(const int* __restrict__ ei, const int* __restrict__ row_beg,
                          int* __restrict__ cur, const float* __restrict__ dinv,
                          Edge* __restrict__ csr, int E) {
    int e = blockIdx.x * blockDim.x + threadIdx.x;
    if (e < E) {
        int s = ei[e];
        int d = ei[E + e];
        int pos = atomicAdd(&cur[d], 1);
        float2 rec = make_float2(__int_as_float(s), dinv[s] * dinv[d]);
        *reinterpret_cast<float2*>(&csr[row_beg[d] + pos]) = rec;
    }
}

// ---------------- vector row load helper ----------------

template <int VW>
__device__ __forceinline__ void ldrow(float (&f)[VW], const float* __restrict__ p) {
    if (VW == 4) { float4 t = *(const float4*)p; f[0]=t.x; f[1]=t.y; f[2]=t.z; f[3]=t.w; }
    else if (VW == 2) { float2 t = *(const float2*)p; f[0]=t.x; f[1]=t.y; }
    else { f[0] = *p; }
}

// ---------------- fused CSR aggregation (dense thread mapping) ----------------

template <int C, int VW, int SIN, int SOUT>
__global__ void k_agg(const float* __restrict__ h, const int* __restrict__ row_beg,
                      const int* __restrict__ ideg,
                      const Edge* __restrict__ csr, const float* __restrict__ dinv,
                      const float* __restrict__ bias, float* __restrict__ out, int n) {
    constexpr int L = C / VW;
    constexpr int TPN = SOUT / VW;
    int t = blockIdx.x * blockDim.x + threadIdx.x;
    int v = t / TPN;
    int r = t - v * TPN;
    if (v >= n) return;

    if (r < L) {
        int beg = row_beg[v];
        int endp = beg + ((ideg[v] + 3) & ~3);
        const int off = r * VW;

        float dv = dinv[v];
        float pvv[VW];
        ldrow<VW>(pvv, h + v * SIN + off);

        float acc[VW];
#pragma unroll
        for (int k = 0; k < VW; k++) acc[k] = 0.f;

        int j = beg;
        for (; j + 8 <= endp; j += 8) {
            int4 e0 = *(const int4*)(csr + j);
            int4 e1 = *(const int4*)(csr + j + 2);
            int4 e2 = *(const int4*)(csr + j + 4);
            int4 e3 = *(const int4*)(csr + j + 6);
            float f[8][VW];
            ldrow<VW>(f[0], h + e0.x * SIN + off);
            ldrow<VW>(f[1], h + e0.z * SIN + off);
            ldrow<VW>(f[2], h + e1.x * SIN + off);
            ldrow<VW>(f[3], h + e1.z * SIN + off);
            ldrow<VW>(f[4], h + e2.x * SIN + off);
            ldrow<VW>(f[5], h + e2.z * SIN + off);
            ldrow<VW>(f[6], h + e3.x * SIN + off);
            ldrow<VW>(f[7], h + e3.z * SIN + off);
            float w[8];
            w[0] = __int_as_float(e0.y); w[1] = __int_as_float(e0.w);
            w[2] = __int_as_float(e1.y); w[3] = __int_as_float(e1.w);
            w[4] = __int_as_float(e2.y); w[5] = __int_as_float(e2.w);
            w[6] = __int_as_float(e3.y); w[7] = __int_as_float(e3.w);
#pragma unroll
            for (int i = 0; i < 8; i++)
#pragma unroll
                for (int k = 0; k < VW; k++) acc[k] = fmaf(w[i], f[i][k], acc[k]);
        }
        if (j < endp) {
            int4 e0 = *(const int4*)(csr + j);
            int4 e1 = *(const int4*)(csr + j + 2);
            float f[4][VW];
            ldrow<VW>(f[0], h + e0.x * SIN + off);
            ldrow<VW>(f[1], h + e0.z * SIN + off);
            ldrow<VW>(f[2], h + e1.x * SIN + off);
            ldrow<VW>(f[3], h + e1.z * SIN + off);
            float w[4];
            w[0] = __int_as_float(e0.y); w[1] = __int_as_float(e0.w);
            w[2] = __int_as_float(e1.y); w[3] = __int_as_float(e1.w);
#pragma unroll
            for (int i = 0; i < 4; i++)
#pragma unroll
                for (int k = 0; k < VW; k++) acc[k] = fmaf(w[i], f[i][k], acc[k]);
        }

        float s2 = dv * dv;
        float* po = out + v * SOUT + off;
#pragma unroll
        for (int k = 0; k < VW; k++) {
            float r2 = fmaf(s2, pvv[k], acc[k]);
            if (bias) r2 = fmaxf(r2 + bias[off + k], 0.f);
            po[k] = r2;
        }
    } else {
        float* po = out + v * SOUT + r * VW;
#pragma unroll
        for (int k = 0; k < VW; k++) po[k] = 0.f;
    }
}

// ---------------- scalar GEMM (layers 1, 4 — exact fp32) ----------------

#define GBM 256
#define GBN 32
#define GBK 16

__global__ void __launch_bounds__(256)
k_gemm(const float* __restrict__ A, const float* __restrict__ W,
       const float* __restrict__ bias, float* __restrict__ Cout,
       int N, int K, int M, int SA, int SC, int fuse_bias_relu) {
    __shared__ float As[GBK][GBM];
    __shared__ float Bs[GBK][GBN];

    int tid = threadIdx.x;
    int bm = blockIdx.x * GBM;
    int bn = blockIdx.y * GBN;
    int ty = tid >> 3;
    int tx = tid & 7;
    int row0 = ty * 8;
    int col0 = tx * 4;

    float acc[8][4];
#pragma unroll
    for (int i = 0; i < 8; i++)
#pragma unroll
        for (int j = 0; j < 4; j++) acc[i][j] = 0.f;

    for (int k0 = 0; k0 < K; k0 += GBK) {
#pragma unroll
        for (int i = 0; i < 4; i++) {
            int lin4 = tid + i * 256;
            int r = lin4 >> 2;
            int kk4 = lin4 & 3;
            int gr = bm + r;
            int gk0 = k0 + kk4 * 4;
            float4 a = make_float4(0.f, 0.f, 0.f, 0.f);
            if (gr < N && gk0 + 3 < SA)
                a = *(const float4*)(A + (size_t)gr * SA + gk0);
            As[kk4 * 4 + 0][r] = a.x;
            As[kk4 * 4 + 1][r] = a.y;
            As[kk4 * 4 + 2][r] = a.z;
            As[kk4 * 4 + 3][r] = a.w;
        }
#pragma unroll
        for (int i = 0; i < 2; i++) {
            int lin = tid + i * 256;
            int r = lin >> 5;
            int c = lin & 31;
            int gk = k0 + r, gc = bn + c;
            Bs[r][c] = (gk < K && gc < M) ? W[(size_t)gk * M + gc] : 0.f;
        }
        __syncthreads();

#pragma unroll
        for (int kk = 0; kk < GBK; kk++) {
            float4 a0 = *(const float4*)&As[kk][row0];
            float4 a1 = *(const float4*)&As[kk][row0 + 4];
            float4 b  = *(const float4*)&Bs[kk][col0];
            float av[8] = {a0.x, a0.y, a0.z, a0.w, a1.x, a1.y, a1.z, a1.w};
            float bv[4] = {b.x, b.y, b.z, b.w};
#pragma unroll
            for (int i = 0; i < 8; i++)
#pragma unroll
                for (int j = 0; j < 4; j++) acc[i][j] = fmaf(av[i], bv[j], acc[i][j]);
        }
        __syncthreads();
    }

#pragma unroll
    for (int i = 0; i < 8; i++) {
        int gr = bm + row0 + i;
        if (gr < N) {
#pragma unroll
            for (int j = 0; j < 4; j++) {
                int gc = bn + col0 + j;
                if (gc < M) {
                    float v = acc[i][j];
                    if (fuse_bias_relu) v = fmaxf(v + bias[gc], 0.f);
                    Cout[(size_t)gr * SC + gc] = v;
                }
            }
        }
    }
}

// ---------------- tf32 tensor-core GEMM (layers 2, 3) ----------------
// C[N x M] = A[N x K] @ W[K x M]; mma.m16n8k8.tf32, fp32 accumulate.
// 128 threads = 4 warps; block tile 128 rows x 32 cols; warp tile 32x32.

__device__ __forceinline__ uint32_t f2tf32(float x) {
    uint32_t r;
    asm("cvt.rna.tf32.f32 %0, %1;" : "=r"(r) : "f"(x));
    return r;
}

#define TAS 132   // padded smem row stride (conflict-free frag reads)

__global__ void __launch_bounds__(128)
k_gemm_tc(const float* __restrict__ A, const float* __restrict__ W,
          float* __restrict__ Cout, int N, int K, int M, int SA, int SC) {
    __shared__ float As[8][TAS];          // [k][row], tf32-converted

    int tid = threadIdx.x;
    int warp = tid >> 5;
    int lane = tid & 31;
    int g  = lane >> 2;                   // groupID 0..7
    int tg = lane & 3;                    // thread-in-group 0..3
    int bm = blockIdx.x * 128;
    int bn = blockIdx.y * 32;
    int wr = warp * 32;

    float c[2][4][4];
#pragma unroll
    for (int mt = 0; mt < 2; mt++)
#pragma unroll
        for (int t = 0; t < 4; t++)
#pragma unroll
            for (int q = 0; q < 4; q++) c[mt][t][q] = 0.f;

    int ksteps = (K + 7) >> 3;
    for (int ks = 0; ks < ksteps; ks++) {
        int k0 = ks << 3;
        // stage A slice: thread i -> row bm+i, cols k0..k0+7 (2x float4, aligned)
        {
            int gr = bm + tid;
            float4 a0 = make_float4(0.f, 0.f, 0.f, 0.f);
            float4 a1 = a0;
            if (gr < N) {
                const float* p = A + (size_t)gr * SA + k0;
                a0 = *(const float4*)p;
                a1 = *(const float4*)(p + 4);
            }
            As[0][tid] = __uint_as_float(f2tf32(a0.x));
            As[1][tid] = __uint_as_float(f2tf32(a0.y));
            As[2][tid] = __uint_as_float(f2tf32(a0.z));
            As[3][tid] = __uint_as_float(f2tf32(a0.w));
            As[4][tid] = __uint_as_float(f2tf32(a1.x));
            As[5][tid] = __uint_as_float(f2tf32(a1.y));
            As[6][tid] = __uint_as_float(f2tf32(a1.z));
            As[7][tid] = __uint_as_float(f2tf32(a1.w));
        }
        __syncthreads();

        // B fragments: n-tile t covers cols bn + t*8 .. +7; zero-fill beyond K/M
        uint32_t bfr[4][2];
#pragma unroll
        for (int t = 0; t < 4; t++) {
            int col = bn + t * 8 + g;
            int r0 = k0 + tg;
            int r1 = r0 + 4;
            float b0 = (r0 < K && col < M) ? W[(size_t)r0 * M + col] : 0.f;
            float b1 = (r1 < K && col < M) ? W[(size_t)r1 * M + col] : 0.f;
            bfr[t][0] = f2tf32(b0);
            bfr[t][1] = f2tf32(b1);
        }

#pragma unroll
        for (int mt = 0; mt < 2; mt++) {
            int r = wr + mt * 16 + g;
            uint32_t a0 = __float_as_uint(As[tg][r]);
            uint32_t a1 = __float_as_uint(As[tg][r + 8]);
            uint32_t a2 = __float_as_uint(As[tg + 4][r]);
            uint32_t a3 = __float_as_uint(As[tg + 4][r + 8]);
#pragma unroll
            for (int t = 0; t < 4; t++) {
                asm volatile(
                    "mma.sync.aligned.m16n8k8.row.col.f32.tf32.tf32.f32 "
                    "{%0,%1,%2,%3}, {%4,%5,%6,%7}, {%8,%9}, {%0,%1,%2,%3};"
                    : "+f"(c[mt][t][0]), "+f"(c[mt][t][1]),
                      "+f"(c[mt][t][2]), "+f"(c[mt][t][3])
                    : "r"(a0), "r"(a1), "r"(a2), "r"(a3),
                      "r"(bfr[t][0]), "r"(bfr[t][1]));
            }
        }
        __syncthreads();
    }

    // epilogue: c0,c1 -> row g,   cols 2*tg, 2*tg+1
    //           c2,c3 -> row g+8, same cols  (M even -> pair store ok)
#pragma unroll
    for (int mt = 0; mt < 2; mt++) {
#pragma unroll
        for (int t = 0; t < 4; t++) {
            int col = bn + t * 8 + 2 * tg;
            if (col + 1 < M || col < M) {
                int r0 = bm + wr + mt * 16 + g;
                if (col + 1 < M) {
                    if (r0 < N)
                        *(float2*)(Cout + (size_t)r0 * SC + col) =
                            make_float2(c[mt][t][0], c[mt][t][1]);
                    if (r0 + 8 < N)
                        *(float2*)(Cout + (size_t)(r0 + 8) * SC + col) =
                            make_float2(c[mt][t][2], c[mt][t][3]);
                } else {                     // col == M-1 (M odd; not hit for 84/42)
                    if (r0 < N) Cout[(size_t)r0 * SC + col] = c[mt][t][0];
                    if (r0 + 8 < N) Cout[(size_t)(r0 + 8) * SC + col] = c[mt][t][2];
                }
            }
        }
    }
}

// ---------------- final: CSR agg + bias + relu + log_softmax (warp/node) --------

__global__ void k_final(const float* __restrict__ t4,       // stride 24
                        const int* __restrict__ row_beg,
                        const int* __restrict__ ideg,
                        const Edge* __restrict__ csr,
                        const float* __restrict__ dinv,
                        const float* __restrict__ b4,
                        float* __restrict__ out_z, float* __restrict__ out_pz, int n) {
    int v = (blockIdx.x * blockDim.x + threadIdx.x) >> 5;
    int lane = threadIdx.x & 31;
    if (v >= n) return;

    float val = -INFINITY;
    if (lane < 21) {
        int beg = row_beg[v];
        int endp = beg + ((ideg[v] + 3) & ~3);
        float dv = dinv[v];
        float selfv = t4[v * 24 + lane];
        float acc = 0.f;

        int j = beg;
        for (; j + 8 <= endp; j += 8) {
            int4 e0 = *(const int4*)(csr + j);
            int4 e1 = *(const int4*)(csr + j + 2);
            int4 e2 = *(const int4*)(csr + j + 4);
            int4 e3 = *(const int4*)(csr + j + 6);
            float f0 = t4[e0.x * 24 + lane];
            float f1 = t4[e0.z * 24 + lane];
            float f2 = t4[e1.x * 24 + lane];
            float f3 = t4[e1.z * 24 + lane];
            float f4 = t4[e2.x * 24 + lane];
            float f5 = t4[e2.z * 24 + lane];
            float f6 = t4[e3.x * 24 + lane];
            float f7 = t4[e3.z * 24 + lane];
            acc = fmaf(__int_as_float(e0.y), f0, acc);
            acc = fmaf(__int_as_float(e0.w), f1, acc);
            acc = fmaf(__int_as_float(e1.y), f2, acc);
            acc = fmaf(__int_as_float(e1.w), f3, acc);
            acc = fmaf(__int_as_float(e2.y), f4, acc);
            acc = fmaf(__int_as_float(e2.w), f5, acc);
            acc = fmaf(__int_as_float(e3.y), f6, acc);
            acc = fmaf(__int_as_float(e3.w), f7, acc);
        }
        if (j < endp) {
            int4 e0 = *(const int4*)(csr + j);
            int4 e1 = *(const int4*)(csr + j + 2);
            float f0 = t4[e0.x * 24 + lane];
            float f1 = t4[e0.z * 24 + lane];
            float f2 = t4[e1.x * 24 + lane];
            float f3 = t4[e1.z * 24 + lane];
            acc = fmaf(__int_as_float(e0.y), f0, acc);
            acc = fmaf(__int_as_float(e0.w), f1, acc);
            acc = fmaf(__int_as_float(e1.y), f2, acc);
            acc = fmaf(__int_as_float(e1.w), f3, acc);
        }
        acc = fmaf(dv * dv, selfv, acc);
        val = fmaxf(acc + b4[lane], 0.f);
    }

    float m = val;
#pragma unroll
    for (int o = 16; o > 0; o >>= 1) m = fmaxf(m, __shfl_xor_sync(0xffffffffu, m, o));
    float ex = (lane < 21) ? __expf(val - m) : 0.f;
    float s = ex;
#pragma unroll
    for (int o = 16; o > 0; o >>= 1) s += __shfl_xor_sync(0xffffffffu, s, o);

    if (lane < 21) {
        out_z[v * 21 + lane] = val;
        out_pz[v * 21 + lane] = val - m - __logf(s);
    }
}

// ---------------------------------------------------------------------------

static inline int cdiv(long long a, int b) { return (int)((a + b - 1) / b); }

extern "C" void kernel_launch(void* const* d_in, const int* in_sizes, int n_in,
                              void* d_out, int out_size) {
    const float* x  = (const float*)d_in[0];
    const int*   ei = (const int*)d_in[1];
    const float* W1 = (const float*)d_in[2];  const float* b1 = (const float*)d_in[3];
    const float* W2 = (const float*)d_in[4];  const float* b2 = (const float*)d_in[5];
    const float* W3 = (const float*)d_in[6];  const float* b3 = (const float*)d_in[7];
    const float* W4 = (const float*)d_in[8];  const float* b4 = (const float*)d_in[9];

    const int n = in_sizes[0] / 21;
    const int E = in_sizes[1] / 2;

    float *bufA, *bufB, *dinv;
    int *ideg, *row_beg, *cur, *counter;
    Edge* csr;
    cudaGetSymbolAddress((void**)&bufA, g_bufA);
    cudaGetSymbolAddress((void**)&bufB, g_bufB);
    cudaGetSymbolAddress((void**)&dinv, g_dinv);
    cudaGetSymbolAddress((void**)&ideg, g_ideg);
    cudaGetSymbolAddress((void**)&row_beg, g_rowbeg);
    cudaGetSymbolAddress((void**)&cur, g_cur);
    cudaGetSymbolAddress((void**)&counter, g_counter);
    cudaGetSymbolAddress((void**)&csr, g_csr);

    float* out_pz = (float*)d_out;
    float* out_z  = (float*)d_out + (size_t)n * 21;

    const int T = 256;
    const int nb = cdiv(n, SCAN_B);

    // --- CSR build (4 launches) ---
    k_init<<<cdiv(n, T), T>>>(ideg, cur, counter, n);
    k_count_deg<<<cdiv(E, T), T>>>(ei, ideg, E);
    k_offsets<<<nb, SCAN_B>>>(ideg, row_beg, dinv, csr, counter, n);
    k_scatter<<<cdiv(E, T), T>>>(ei, row_beg, cur, dinv, csr, E);

    // --- layer 1: dense agg of x (C=21, TPN=24), scalar GEMM 21->168 (+bias+relu) ---
    k_agg<21, 1, 21, 24><<<cdiv((long long)n * 24, T), T>>>(
        x, row_beg, ideg, csr, dinv, nullptr, bufA, n);
    {
        dim3 grid(cdiv(n, GBM), cdiv(168, GBN));
        k_gemm<<<grid, T>>>(bufA, W1, b1, bufB, n, 21, 168, 24, 168, 1);
    }
    // --- layer 2: tf32 TC GEMM 168->84, dense agg+bias+relu (C=84, VW=4) ---
    {
        dim3 grid(cdiv(n, 128), cdiv(84, 32));
        k_gemm_tc<<<grid, 128>>>(bufB, W2, bufA, n, 168, 84, 168, 84);
    }
    k_agg<84, 4, 84, 84><<<cdiv((long long)n * 21, T), T>>>(
        bufA, row_beg, ideg, csr, dinv, b2, bufB, n);
    // --- layer 3: tf32 TC GEMM 84->42 (out stride 44), dense agg (C=42, VW=2) ---
    {
        dim3 grid(cdiv(n, 128), cdiv(42, 32));
        k_gemm_tc<<<grid, 128>>>(bufB, W3, bufA, n, 84, 42, 84, 44);
    }
    k_agg<42, 2, 44, 44><<<cdiv((long long)n * 22, T), T>>>(
        bufA, row_beg, ideg, csr, dinv, b3, bufB, n);
    // --- layer 4: scalar GEMM 42->21 (out stride 24), fused final ---
    {
        dim3 grid(cdiv(n, GBM), cdiv(21, GBN));
        k_gemm<<<grid, T>>>(bufB, W4, nullptr, bufA, n, 42, 21, 44, 24, 0);
    }
    k_final<<<cdiv((long long)n * 32, T), T>>>(
        bufA, row_beg, ideg, csr, dinv, b4, out_z, out_pz, n);
}

// round 12
// speedup vs baseline: 1.4538x; 1.0847x over previous
#include <cuda_runtime.h>
#include <math.h>
#include <stdint.h>

// ---------------------------------------------------------------------------
// graphNet: 4-layer GCN (21->168->84->42->21) + log_softmax.
// Round-12: R11 base (397.3us) + tf32 TC GEMM for layer 1 as well (with
// fused bias+relu epilogue). Layer 4 stays exact fp32 (feeds softmax, tiny).
// Dense agg mapping, GRP=8 gather groups, 4-launch CSR build.
// ---------------------------------------------------------------------------

#define N_MAX 100000
#define E_MAX 1600000
#define F_MAX 168
#define CSR_MAX (E_MAX + 4 * N_MAX)
#define SCAN_B 1024

struct __align__(8) Edge { int src; float w; };

__device__ float g_bufA[(size_t)N_MAX * F_MAX];
__device__ float g_bufB[(size_t)N_MAX * F_MAX];
__device__ int   g_ideg[N_MAX];
__device__ float g_dinv[N_MAX];
__device__ int   g_rowbeg[N_MAX];
__device__ int   g_cur[N_MAX];
__device__ int   g_counter[1];
__device__ Edge  g_csr[CSR_MAX];

// ---------------- init / degree ----------------

__global__ void k_init(int* __restrict__ ideg, int* __restrict__ cur,
                       int* __restrict__ counter, int n) {
    int i = blockIdx.x * blockDim.x + threadIdx.x;
    if (i < n) { ideg[i] = 0; cur[i] = 0; }
    if (i == 0) counter[0] = 0;
}

__global__ void k_count_deg(const int* __restrict__ ei, int* __restrict__ ideg, int E) {
    int e = blockIdx.x * blockDim.x + threadIdx.x;
    if (e < E) atomicAdd(&ideg[ei[E + e]], 1);
}

// ---------------- fused single-pass offsets ----------------

__global__ void k_offsets(const int* __restrict__ ideg, int* __restrict__ row_beg,
                          float* __restrict__ dinv, Edge* __restrict__ csr,
                          int* __restrict__ counter, int n) {
    __shared__ int s[SCAN_B];
    __shared__ int base_sh;
    int i = blockIdx.x * SCAN_B + threadIdx.x;
    int deg = (i < n) ? ideg[i] : 0;
    int pd = (deg + 3) & ~3;
    s[threadIdx.x] = pd;
    __syncthreads();
#pragma unroll
    for (int off = 1; off < SCAN_B; off <<= 1) {
        int t = (threadIdx.x >= off) ? s[threadIdx.x - off] : 0;
        __syncthreads();
        s[threadIdx.x] += t;
        __syncthreads();
    }
    if (threadIdx.x == SCAN_B - 1) base_sh = atomicAdd(counter, s[SCAN_B - 1]);
    __syncthreads();
    int base = base_sh;
    if (i < n) {
        int beg = base + s[threadIdx.x] - pd;
        row_beg[i] = beg;
        dinv[i] = rsqrtf((float)(deg + 1));
        Edge z; z.src = 0; z.w = 0.f;
        for (int p = deg; p < pd; p++) csr[beg + p] = z;
    }
}

// ---------------- CSR scatter ----------------

__global__ void k_scatter(const int* __restrict__ ei, const int* __restrict__ row_beg,
                          int* __restrict__ cur, const float* __restrict__ dinv,
                          Edge* __restrict__ csr, int E) {
    int e = blockIdx.x * blockDim.x + threadIdx.x;
    if (e < E) {
        int s = ei[e];
        int d = ei[E + e];
        int pos = atomicAdd(&cur[d], 1);
        float2 rec = make_float2(__int_as_float(s), dinv[s] * dinv[d]);
        *reinterpret_cast<float2*>(&csr[row_beg[d] + pos]) = rec;
    }
}

// ---------------- vector row load helper ----------------

template <int VW>
__device__ __forceinline__ void ldrow(float (&f)[VW], const float* __restrict__ p) {
    if (VW == 4) { float4 t = *(const float4*)p; f[0]=t.x; f[1]=t.y; f[2]=t.z; f[3]=t.w; }
    else if (VW == 2) { float2 t = *(const float2*)p; f[0]=t.x; f[1]=t.y; }
    else { f[0] = *p; }
}

// ---------------- fused CSR aggregation (dense thread mapping) ----------------

template <int C, int VW, int SIN, int SOUT>
__global__ void k_agg(const float* __restrict__ h, const int* __restrict__ row_beg,
                      const int* __restrict__ ideg,
                      const Edge* __restrict__ csr, const float* __restrict__ dinv,
                      const float* __restrict__ bias, float* __restrict__ out, int n) {
    constexpr int L = C / VW;
    constexpr int TPN = SOUT / VW;
    int t = blockIdx.x * blockDim.x + threadIdx.x;
    int v = t / TPN;
    int r = t - v * TPN;
    if (v >= n) return;

    if (r < L) {
        int beg = row_beg[v];
        int endp = beg + ((ideg[v] + 3) & ~3);
        const int off = r * VW;

        float dv = dinv[v];
        float pvv[VW];
        ldrow<VW>(pvv, h + v * SIN + off);

        float acc[VW];
#pragma unroll
        for (int k = 0; k < VW; k++) acc[k] = 0.f;

        int j = beg;
        for (; j + 8 <= endp; j += 8) {
            int4 e0 = *(const int4*)(csr + j);
            int4 e1 = *(const int4*)(csr + j + 2);
            int4 e2 = *(const int4*)(csr + j + 4);
            int4 e3 = *(const int4*)(csr + j + 6);
            float f[8][VW];
            ldrow<VW>(f[0], h + e0.x * SIN + off);
            ldrow<VW>(f[1], h + e0.z * SIN + off);
            ldrow<VW>(f[2], h + e1.x * SIN + off);
            ldrow<VW>(f[3], h + e1.z * SIN + off);
            ldrow<VW>(f[4], h + e2.x * SIN + off);
            ldrow<VW>(f[5], h + e2.z * SIN + off);
            ldrow<VW>(f[6], h + e3.x * SIN + off);
            ldrow<VW>(f[7], h + e3.z * SIN + off);
            float w[8];
            w[0] = __int_as_float(e0.y); w[1] = __int_as_float(e0.w);
            w[2] = __int_as_float(e1.y); w[3] = __int_as_float(e1.w);
            w[4] = __int_as_float(e2.y); w[5] = __int_as_float(e2.w);
            w[6] = __int_as_float(e3.y); w[7] = __int_as_float(e3.w);
#pragma unroll
            for (int i = 0; i < 8; i++)
#pragma unroll
                for (int k = 0; k < VW; k++) acc[k] = fmaf(w[i], f[i][k], acc[k]);
        }
        if (j < endp) {
            int4 e0 = *(const int4*)(csr + j);
            int4 e1 = *(const int4*)(csr + j + 2);
            float f[4][VW];
            ldrow<VW>(f[0], h + e0.x * SIN + off);
            ldrow<VW>(f[1], h + e0.z * SIN + off);
            ldrow<VW>(f[2], h + e1.x * SIN + off);
            ldrow<VW>(f[3], h + e1.z * SIN + off);
            float w[4];
            w[0] = __int_as_float(e0.y); w[1] = __int_as_float(e0.w);
            w[2] = __int_as_float(e1.y); w[3] = __int_as_float(e1.w);
#pragma unroll
            for (int i = 0; i < 4; i++)
#pragma unroll
                for (int k = 0; k < VW; k++) acc[k] = fmaf(w[i], f[i][k], acc[k]);
        }

        float s2 = dv * dv;
        float* po = out + v * SOUT + off;
#pragma unroll
        for (int k = 0; k < VW; k++) {
            float r2 = fmaf(s2, pvv[k], acc[k]);
            if (bias) r2 = fmaxf(r2 + bias[off + k], 0.f);
            po[k] = r2;
        }
    } else {
        float* po = out + v * SOUT + r * VW;
#pragma unroll
        for (int k = 0; k < VW; k++) po[k] = 0.f;
    }
}

// ---------------- scalar GEMM (layer 4 — exact fp32) ----------------

#define GBM 256
#define GBN 32
#define GBK 16

__global__ void __launch_bounds__(256)
k_gemm(const float* __restrict__ A, const float* __restrict__ W,
       const float* __restrict__ bias, float* __restrict__ Cout,
       int N, int K, int M, int SA, int SC, int fuse_bias_relu) {
    __shared__ float As[GBK][GBM];
    __shared__ float Bs[GBK][GBN];

    int tid = threadIdx.x;
    int bm = blockIdx.x * GBM;
    int bn = blockIdx.y * GBN;
    int ty = tid >> 3;
    int tx = tid & 7;
    int row0 = ty * 8;
    int col0 = tx * 4;

    float acc[8][4];
#pragma unroll
    for (int i = 0; i < 8; i++)
#pragma unroll
        for (int j = 0; j < 4; j++) acc[i][j] = 0.f;

    for (int k0 = 0; k0 < K; k0 += GBK) {
#pragma unroll
        for (int i = 0; i < 4; i++) {
            int lin4 = tid + i * 256;
            int r = lin4 >> 2;
            int kk4 = lin4 & 3;
            int gr = bm + r;
            int gk0 = k0 + kk4 * 4;
            float4 a = make_float4(0.f, 0.f, 0.f, 0.f);
            if (gr < N && gk0 + 3 < SA)
                a = *(const float4*)(A + (size_t)gr * SA + gk0);
            As[kk4 * 4 + 0][r] = a.x;
            As[kk4 * 4 + 1][r] = a.y;
            As[kk4 * 4 + 2][r] = a.z;
            As[kk4 * 4 + 3][r] = a.w;
        }
#pragma unroll
        for (int i = 0; i < 2; i++) {
            int lin = tid + i * 256;
            int r = lin >> 5;
            int c = lin & 31;
            int gk = k0 + r, gc = bn + c;
            Bs[r][c] = (gk < K && gc < M) ? W[(size_t)gk * M + gc] : 0.f;
        }
        __syncthreads();

#pragma unroll
        for (int kk = 0; kk < GBK; kk++) {
            float4 a0 = *(const float4*)&As[kk][row0];
            float4 a1 = *(const float4*)&As[kk][row0 + 4];
            float4 b  = *(const float4*)&Bs[kk][col0];
            float av[8] = {a0.x, a0.y, a0.z, a0.w, a1.x, a1.y, a1.z, a1.w};
            float bv[4] = {b.x, b.y, b.z, b.w};
#pragma unroll
            for (int i = 0; i < 8; i++)
#pragma unroll
                for (int j = 0; j < 4; j++) acc[i][j] = fmaf(av[i], bv[j], acc[i][j]);
        }
        __syncthreads();
    }

#pragma unroll
    for (int i = 0; i < 8; i++) {
        int gr = bm + row0 + i;
        if (gr < N) {
#pragma unroll
            for (int j = 0; j < 4; j++) {
                int gc = bn + col0 + j;
                if (gc < M) {
                    float v = acc[i][j];
                    if (fuse_bias_relu) v = fmaxf(v + bias[gc], 0.f);
                    Cout[(size_t)gr * SC + gc] = v;
                }
            }
        }
    }
}

// ---------------- tf32 tensor-core GEMM (layers 1, 2, 3) ----------------
// C[N x M] = A[N x K] @ W[K x M]; mma.m16n8k8.tf32, fp32 accumulate.
// 128 threads = 4 warps; block tile 128 rows x 32 cols; warp tile 32x32.
// Optional fused bias+relu epilogue.

__device__ __forceinline__ uint32_t f2tf32(float x) {
    uint32_t r;
    asm("cvt.rna.tf32.f32 %0, %1;" : "=r"(r) : "f"(x));
    return r;
}

#define TAS 132   // padded smem row stride (conflict-free frag reads)

__global__ void __launch_bounds__(128)
k_gemm_tc(const float* __restrict__ A, const float* __restrict__ W,
          const float* __restrict__ bias, float* __restrict__ Cout,
          int N, int K, int M, int SA, int SC, int fuse_bias_relu) {
    __shared__ float As[8][TAS];          // [k][row], tf32-converted

    int tid = threadIdx.x;
    int warp = tid >> 5;
    int lane = tid & 31;
    int g  = lane >> 2;                   // groupID 0..7
    int tg = lane & 3;                    // thread-in-group 0..3
    int bm = blockIdx.x * 128;
    int bn = blockIdx.y * 32;
    int wr = warp * 32;

    float c[2][4][4];
#pragma unroll
    for (int mt = 0; mt < 2; mt++)
#pragma unroll
        for (int t = 0; t < 4; t++)
#pragma unroll
            for (int q = 0; q < 4; q++) c[mt][t][q] = 0.f;

    int ksteps = (K + 7) >> 3;
    for (int ks = 0; ks < ksteps; ks++) {
        int k0 = ks << 3;
        // stage A slice: thread i -> row bm+i, cols k0..k0+7 (2x float4, aligned)
        {
            int gr = bm + tid;
            float4 a0 = make_float4(0.f, 0.f, 0.f, 0.f);
            float4 a1 = a0;
            if (gr < N) {
                const float* p = A + (size_t)gr * SA + k0;
                a0 = *(const float4*)p;
                a1 = *(const float4*)(p + 4);
            }
            As[0][tid] = __uint_as_float(f2tf32(a0.x));
            As[1][tid] = __uint_as_float(f2tf32(a0.y));
            As[2][tid] = __uint_as_float(f2tf32(a0.z));
            As[3][tid] = __uint_as_float(f2tf32(a0.w));
            As[4][tid] = __uint_as_float(f2tf32(a1.x));
            As[5][tid] = __uint_as_float(f2tf32(a1.y));
            As[6][tid] = __uint_as_float(f2tf32(a1.z));
            As[7][tid] = __uint_as_float(f2tf32(a1.w));
        }
        __syncthreads();

        // B fragments: n-tile t covers cols bn + t*8 .. +7; zero-fill beyond K/M
        uint32_t bfr[4][2];
#pragma unroll
        for (int t = 0; t < 4; t++) {
            int col = bn + t * 8 + g;
            int r0 = k0 + tg;
            int r1 = r0 + 4;
            float b0 = (r0 < K && col < M) ? W[(size_t)r0 * M + col] : 0.f;
            float b1 = (r1 < K && col < M) ? W[(size_t)r1 * M + col] : 0.f;
            bfr[t][0] = f2tf32(b0);
            bfr[t][1] = f2tf32(b1);
        }

#pragma unroll
        for (int mt = 0; mt < 2; mt++) {
            int r = wr + mt * 16 + g;
            uint32_t a0 = __float_as_uint(As[tg][r]);
            uint32_t a1 = __float_as_uint(As[tg][r + 8]);
            uint32_t a2 = __float_as_uint(As[tg + 4][r]);
            uint32_t a3 = __float_as_uint(As[tg + 4][r + 8]);
#pragma unroll
            for (int t = 0; t < 4; t++) {
                asm volatile(
                    "mma.sync.aligned.m16n8k8.row.col.f32.tf32.tf32.f32 "
                    "{%0,%1,%2,%3}, {%4,%5,%6,%7}, {%8,%9}, {%0,%1,%2,%3};"
                    : "+f"(c[mt][t][0]), "+f"(c[mt][t][1]),
                      "+f"(c[mt][t][2]), "+f"(c[mt][t][3])
                    : "r"(a0), "r"(a1), "r"(a2), "r"(a3),
                      "r"(bfr[t][0]), "r"(bfr[t][1]));
            }
        }
        __syncthreads();
    }

    // epilogue: c0,c1 -> row g, cols 2*tg,2*tg+1; c2,c3 -> row g+8, same cols
#pragma unroll
    for (int mt = 0; mt < 2; mt++) {
#pragma unroll
        for (int t = 0; t < 4; t++) {
            int col = bn + t * 8 + 2 * tg;
            int r0 = bm + wr + mt * 16 + g;
            float v0 = c[mt][t][0], v1 = c[mt][t][1];
            float v2 = c[mt][t][2], v3 = c[mt][t][3];
            if (fuse_bias_relu) {
                if (col < M) {
                    float bb0 = bias[col];
                    v0 = fmaxf(v0 + bb0, 0.f);
                    v2 = fmaxf(v2 + bb0, 0.f);
                }
                if (col + 1 < M) {
                    float bb1 = bias[col + 1];
                    v1 = fmaxf(v1 + bb1, 0.f);
                    v3 = fmaxf(v3 + bb1, 0.f);
                }
            }
            if (col + 1 < M) {
                if (r0 < N)
                    *(float2*)(Cout + (size_t)r0 * SC + col) = make_float2(v0, v1);
                if (r0 + 8 < N)
                    *(float2*)(Cout + (size_t)(r0 + 8) * SC + col) = make_float2(v2, v3);
            } else if (col < M) {
                if (r0 < N) Cout[(size_t)r0 * SC + col] = v0;
                if (r0 + 8 < N) Cout[(size_t)(r0 + 8) * SC + col] = v2;
            }
        }
    }
}

// ---------------- final: CSR agg + bias + relu + log_softmax (warp/node) --------

__global__ void k_final(const float* __restrict__ t4,       // stride 24
                        const int* __restrict__ row_beg,
                        const int* __restrict__ ideg,
                        const Edge* __restrict__ csr,
                        const float* __restrict__ dinv,
                        const float* __restrict__ b4,
                        float* __restrict__ out_z, float* __restrict__ out_pz, int n) {
    int v = (blockIdx.x * blockDim.x + threadIdx.x) >> 5;
    int lane = threadIdx.x & 31;
    if (v >= n) return;

    float val = -INFINITY;
    if (lane < 21) {
        int beg = row_beg[v];
        int endp = beg + ((ideg[v] + 3) & ~3);
        float dv = dinv[v];
        float selfv = t4[v * 24 + lane];
        float acc = 0.f;

        int j = beg;
        for (; j + 8 <= endp; j += 8) {
            int4 e0 = *(const int4*)(csr + j);
            int4 e1 = *(const int4*)(csr + j + 2);
            int4 e2 = *(const int4*)(csr + j + 4);
            int4 e3 = *(const int4*)(csr + j + 6);
            float f0 = t4[e0.x * 24 + lane];
            float f1 = t4[e0.z * 24 + lane];
            float f2 = t4[e1.x * 24 + lane];
            float f3 = t4[e1.z * 24 + lane];
            float f4 = t4[e2.x * 24 + lane];
            float f5 = t4[e2.z * 24 + lane];
            float f6 = t4[e3.x * 24 + lane];
            float f7 = t4[e3.z * 24 + lane];
            acc = fmaf(__int_as_float(e0.y), f0, acc);
            acc = fmaf(__int_as_float(e0.w), f1, acc);
            acc = fmaf(__int_as_float(e1.y), f2, acc);
            acc = fmaf(__int_as_float(e1.w), f3, acc);
            acc = fmaf(__int_as_float(e2.y), f4, acc);
            acc = fmaf(__int_as_float(e2.w), f5, acc);
            acc = fmaf(__int_as_float(e3.y), f6, acc);
            acc = fmaf(__int_as_float(e3.w), f7, acc);
        }
        if (j < endp) {
            int4 e0 = *(const int4*)(csr + j);
            int4 e1 = *(const int4*)(csr + j + 2);
            float f0 = t4[e0.x * 24 + lane];
            float f1 = t4[e0.z * 24 + lane];
            float f2 = t4[e1.x * 24 + lane];
            float f3 = t4[e1.z * 24 + lane];
            acc = fmaf(__int_as_float(e0.y), f0, acc);
            acc = fmaf(__int_as_float(e0.w), f1, acc);
            acc = fmaf(__int_as_float(e1.y), f2, acc);
            acc = fmaf(__int_as_float(e1.w), f3, acc);
        }
        acc = fmaf(dv * dv, selfv, acc);
        val = fmaxf(acc + b4[lane], 0.f);
    }

    float m = val;
#pragma unroll
    for (int o = 16; o > 0; o >>= 1) m = fmaxf(m, __shfl_xor_sync(0xffffffffu, m, o));
    float ex = (lane < 21) ? __expf(val - m) : 0.f;
    float s = ex;
#pragma unroll
    for (int o = 16; o > 0; o >>= 1) s += __shfl_xor_sync(0xffffffffu, s, o);

    if (lane < 21) {
        out_z[v * 21 + lane] = val;
        out_pz[v * 21 + lane] = val - m - __logf(s);
    }
}

// ---------------------------------------------------------------------------

static inline int cdiv(long long a, int b) { return (int)((a + b - 1) / b); }

extern "C" void kernel_launch(void* const* d_in, const int* in_sizes, int n_in,
                              void* d_out, int out_size) {
    const float* x  = (const float*)d_in[0];
    const int*   ei = (const int*)d_in[1];
    const float* W1 = (const float*)d_in[2];  const float* b1 = (const float*)d_in[3];
    const float* W2 = (const float*)d_in[4];  const float* b2 = (const float*)d_in[5];
    const float* W3 = (const float*)d_in[6];  const float* b3 = (const float*)d_in[7];
    const float* W4 = (const float*)d_in[8];  const float* b4 = (const float*)d_in[9];

    const int n = in_sizes[0] / 21;
    const int E = in_sizes[1] / 2;

    float *bufA, *bufB, *dinv;
    int *ideg, *row_beg, *cur, *counter;
    Edge* csr;
    cudaGetSymbolAddress((void**)&bufA, g_bufA);
    cudaGetSymbolAddress((void**)&bufB, g_bufB);
    cudaGetSymbolAddress((void**)&dinv, g_dinv);
    cudaGetSymbolAddress((void**)&ideg, g_ideg);
    cudaGetSymbolAddress((void**)&row_beg, g_rowbeg);
    cudaGetSymbolAddress((void**)&cur, g_cur);
    cudaGetSymbolAddress((void**)&counter, g_counter);
    cudaGetSymbolAddress((void**)&csr, g_csr);

    float* out_pz = (float*)d_out;
    float* out_z  = (float*)d_out + (size_t)n * 21;

    const int T = 256;
    const int nb = cdiv(n, SCAN_B);

    // --- CSR build (4 launches) ---
    k_init<<<cdiv(n, T), T>>>(ideg, cur, counter, n);
    k_count_deg<<<cdiv(E, T), T>>>(ei, ideg, E);
    k_offsets<<<nb, SCAN_B>>>(ideg, row_beg, dinv, csr, counter, n);
    k_scatter<<<cdiv(E, T), T>>>(ei, row_beg, cur, dinv, csr, E);

    // --- layer 1: dense agg of x (C=21, TPN=24), TC GEMM 21->168 (+bias+relu) ---
    k_agg<21, 1, 21, 24><<<cdiv((long long)n * 24, T), T>>>(
        x, row_beg, ideg, csr, dinv, nullptr, bufA, n);
    {
        dim3 grid(cdiv(n, 128), cdiv(168, 32));
        k_gemm_tc<<<grid, 128>>>(bufA, W1, b1, bufB, n, 21, 168, 24, 168, 1);
    }
    // --- layer 2: TC GEMM 168->84, dense agg+bias+relu (C=84, VW=4) ---
    {
        dim3 grid(cdiv(n, 128), cdiv(84, 32));
        k_gemm_tc<<<grid, 128>>>(bufB, W2, nullptr, bufA, n, 168, 84, 168, 84, 0);
    }
    k_agg<84, 4, 84, 84><<<cdiv((long long)n * 21, T), T>>>(
        bufA, row_beg, ideg, csr, dinv, b2, bufB, n);
    // --- layer 3: TC GEMM 84->42 (out stride 44), dense agg (C=42, VW=2) ---
    {
        dim3 grid(cdiv(n, 128), cdiv(42, 32));
        k_gemm_tc<<<grid, 128>>>(bufB, W3, nullptr, bufA, n, 84, 42, 84, 44, 0);
    }
    k_agg<42, 2, 44, 44><<<cdiv((long long)n * 22, T), T>>>(
        bufA, row_beg, ideg, csr, dinv, b3, bufB, n);
    // --- layer 4: scalar GEMM 42->21 (out stride 24), fused final ---
    {
        dim3 grid(cdiv(n, GBM), cdiv(21, GBN));
        k_gemm<<<grid, T>>>(bufB, W4, nullptr, bufA, n, 42, 21, 44, 24, 0);
    }
    k_final<<<cdiv((long long)n * 32, T), T>>>(
        bufA, row_beg, ideg, csr, dinv, b4, out_z, out_pz, n);
}

// round 13
// speedup vs baseline: 1.5089x; 1.0379x over previous
#include <cuda_runtime.h>
#include <cuda_fp16.h>
#include <math.h>
#include <stdint.h>

// ---------------------------------------------------------------------------
// graphNet: 4-layer GCN (21->168->84->42->21) + log_softmax.
// Round-13: R12 base (366.3us) + fp16 storage for the layer-2 agg input
// (t2 = h1@W2 stored as half; gathered as half, accumulated fp32) — halves
// the dominant 538MB gather stream. tf32 TC GEMMs layers 1-3, scalar layer 4.
// ---------------------------------------------------------------------------

#define N_MAX 100000
#define E_MAX 1600000
#define F_MAX 168
#define CSR_MAX (E_MAX + 4 * N_MAX)
#define SCAN_B 1024

struct __align__(8) Edge { int src; float w; };

__device__ float  g_bufA[(size_t)N_MAX * F_MAX];
__device__ float  g_bufB[(size_t)N_MAX * F_MAX];
__device__ __half g_bufH[(size_t)N_MAX * 84];       // t2 in fp16
__device__ int    g_ideg[N_MAX];
__device__ float  g_dinv[N_MAX];
__device__ int    g_rowbeg[N_MAX];
__device__ int    g_cur[N_MAX];
__device__ int    g_counter[1];
__device__ Edge   g_csr[CSR_MAX];

// ---------------- init / degree ----------------

__global__ void k_init(int* __restrict__ ideg, int* __restrict__ cur,
                       int* __restrict__ counter, int n) {
    int i = blockIdx.x * blockDim.x + threadIdx.x;
    if (i < n) { ideg[i] = 0; cur[i] = 0; }
    if (i == 0) counter[0] = 0;
}

__global__ void k_count_deg(const int* __restrict__ ei, int* __restrict__ ideg, int E) {
    int e = blockIdx.x * blockDim.x + threadIdx.x;
    if (e < E) atomicAdd(&ideg[ei[E + e]], 1);
}

// ---------------- fused single-pass offsets ----------------

__global__ void k_offsets(const int* __restrict__ ideg, int* __restrict__ row_beg,
                          float* __restrict__ dinv, Edge* __restrict__ csr,
                          int* __restrict__ counter, int n) {
    __shared__ int s[SCAN_B];
    __shared__ int base_sh;
    int i = blockIdx.x * SCAN_B + threadIdx.x;
    int deg = (i < n) ? ideg[i] : 0;
    int pd = (deg + 3) & ~3;
    s[threadIdx.x] = pd;
    __syncthreads();
#pragma unroll
    for (int off = 1; off < SCAN_B; off <<= 1) {
        int t = (threadIdx.x >= off) ? s[threadIdx.x - off] : 0;
        __syncthreads();
        s[threadIdx.x] += t;
        __syncthreads();
    }
    if (threadIdx.x == SCAN_B - 1) base_sh = atomicAdd(counter, s[SCAN_B - 1]);
    __syncthreads();
    int base = base_sh;
    if (i < n) {
        int beg = base + s[threadIdx.x] - pd;
        row_beg[i] = beg;
        dinv[i] = rsqrtf((float)(deg + 1));
        Edge z; z.src = 0; z.w = 0.f;
        for (int p = deg; p < pd; p++) csr[beg + p] = z;
    }
}

// ---------------- CSR scatter ----------------

__global__ void k_scatter(const int* __restrict__ ei, const int* __restrict__ row_beg,
                          int* __restrict__ cur, const float* __restrict__ dinv,
                          Edge* __restrict__ csr, int E) {
    int e = blockIdx.x * blockDim.x + threadIdx.x;
    if (e < E) {
        int s = ei[e];
        int d = ei[E + e];
        int pos = atomicAdd(&cur[d], 1);
        float2 rec = make_float2(__int_as_float(s), dinv[s] * dinv[d]);
        *reinterpret_cast<float2*>(&csr[row_beg[d] + pos]) = rec;
    }
}

// ---------------- vector row load helpers ----------------

template <int VW>
__device__ __forceinline__ void ldrow(float (&f)[VW], const float* __restrict__ p) {
    if (VW == 4) { float4 t = *(const float4*)p; f[0]=t.x; f[1]=t.y; f[2]=t.z; f[3]=t.w; }
    else if (VW == 2) { float2 t = *(const float2*)p; f[0]=t.x; f[1]=t.y; }
    else { f[0] = *p; }
}

__device__ __forceinline__ void ldrow_h4(float (&f)[4], const __half* __restrict__ p) {
    uint2 u = *(const uint2*)p;                        // 4 halves, 8B aligned
    float2 a = __half22float2(*reinterpret_cast<const __half2*>(&u.x));
    float2 b = __half22float2(*reinterpret_cast<const __half2*>(&u.y));
    f[0] = a.x; f[1] = a.y; f[2] = b.x; f[3] = b.y;
}

// ---------------- fused CSR aggregation (dense thread mapping, fp32 in) --------

template <int C, int VW, int SIN, int SOUT>
__global__ void k_agg(const float* __restrict__ h, const int* __restrict__ row_beg,
                      const int* __restrict__ ideg,
                      const Edge* __restrict__ csr, const float* __restrict__ dinv,
                      const float* __restrict__ bias, float* __restrict__ out, int n) {
    constexpr int L = C / VW;
    constexpr int TPN = SOUT / VW;
    int t = blockIdx.x * blockDim.x + threadIdx.x;
    int v = t / TPN;
    int r = t - v * TPN;
    if (v >= n) return;

    if (r < L) {
        int beg = row_beg[v];
        int endp = beg + ((ideg[v] + 3) & ~3);
        const int off = r * VW;

        float dv = dinv[v];
        float pvv[VW];
        ldrow<VW>(pvv, h + v * SIN + off);

        float acc[VW];
#pragma unroll
        for (int k = 0; k < VW; k++) acc[k] = 0.f;

        int j = beg;
        for (; j + 8 <= endp; j += 8) {
            int4 e0 = *(const int4*)(csr + j);
            int4 e1 = *(const int4*)(csr + j + 2);
            int4 e2 = *(const int4*)(csr + j + 4);
            int4 e3 = *(const int4*)(csr + j + 6);
            float f[8][VW];
            ldrow<VW>(f[0], h + e0.x * SIN + off);
            ldrow<VW>(f[1], h + e0.z * SIN + off);
            ldrow<VW>(f[2], h + e1.x * SIN + off);
            ldrow<VW>(f[3], h + e1.z * SIN + off);
            ldrow<VW>(f[4], h + e2.x * SIN + off);
            ldrow<VW>(f[5], h + e2.z * SIN + off);
            ldrow<VW>(f[6], h + e3.x * SIN + off);
            ldrow<VW>(f[7], h + e3.z * SIN + off);
            float w[8];
            w[0] = __int_as_float(e0.y); w[1] = __int_as_float(e0.w);
            w[2] = __int_as_float(e1.y); w[3] = __int_as_float(e1.w);
            w[4] = __int_as_float(e2.y); w[5] = __int_as_float(e2.w);
            w[6] = __int_as_float(e3.y); w[7] = __int_as_float(e3.w);
#pragma unroll
            for (int i = 0; i < 8; i++)
#pragma unroll
                for (int k = 0; k < VW; k++) acc[k] = fmaf(w[i], f[i][k], acc[k]);
        }
        if (j < endp) {
            int4 e0 = *(const int4*)(csr + j);
            int4 e1 = *(const int4*)(csr + j + 2);
            float f[4][VW];
            ldrow<VW>(f[0], h + e0.x * SIN + off);
            ldrow<VW>(f[1], h + e0.z * SIN + off);
            ldrow<VW>(f[2], h + e1.x * SIN + off);
            ldrow<VW>(f[3], h + e1.z * SIN + off);
            float w[4];
            w[0] = __int_as_float(e0.y); w[1] = __int_as_float(e0.w);
            w[2] = __int_as_float(e1.y); w[3] = __int_as_float(e1.w);
#pragma unroll
            for (int i = 0; i < 4; i++)
#pragma unroll
                for (int k = 0; k < VW; k++) acc[k] = fmaf(w[i], f[i][k], acc[k]);
        }

        float s2 = dv * dv;
        float* po = out + v * SOUT + off;
#pragma unroll
        for (int k = 0; k < VW; k++) {
            float r2 = fmaf(s2, pvv[k], acc[k]);
            if (bias) r2 = fmaxf(r2 + bias[off + k], 0.f);
            po[k] = r2;
        }
    } else {
        float* po = out + v * SOUT + r * VW;
#pragma unroll
        for (int k = 0; k < VW; k++) po[k] = 0.f;
    }
}

// ---------------- fp16-input aggregation (layer 2: C=84, VW=4, TPN=21) --------

__global__ void k_agg_h(const __half* __restrict__ h,      // stride 84 halves
                        const int* __restrict__ row_beg,
                        const int* __restrict__ ideg,
                        const Edge* __restrict__ csr, const float* __restrict__ dinv,
                        const float* __restrict__ bias, float* __restrict__ out, int n) {
    int t = blockIdx.x * blockDim.x + threadIdx.x;
    int v = t / 21;
    int r = t - v * 21;
    if (v >= n) return;

    int beg = row_beg[v];
    int endp = beg + ((ideg[v] + 3) & ~3);
    const int off = r * 4;

    float dv = dinv[v];
    float pvv[4];
    ldrow_h4(pvv, h + v * 84 + off);

    float acc[4] = {0.f, 0.f, 0.f, 0.f};

    int j = beg;
    for (; j + 8 <= endp; j += 8) {
        int4 e0 = *(const int4*)(csr + j);
        int4 e1 = *(const int4*)(csr + j + 2);
        int4 e2 = *(const int4*)(csr + j + 4);
        int4 e3 = *(const int4*)(csr + j + 6);
        float f[8][4];
        ldrow_h4(f[0], h + e0.x * 84 + off);
        ldrow_h4(f[1], h + e0.z * 84 + off);
        ldrow_h4(f[2], h + e1.x * 84 + off);
        ldrow_h4(f[3], h + e1.z * 84 + off);
        ldrow_h4(f[4], h + e2.x * 84 + off);
        ldrow_h4(f[5], h + e2.z * 84 + off);
        ldrow_h4(f[6], h + e3.x * 84 + off);
        ldrow_h4(f[7], h + e3.z * 84 + off);
        float w[8];
        w[0] = __int_as_float(e0.y); w[1] = __int_as_float(e0.w);
        w[2] = __int_as_float(e1.y); w[3] = __int_as_float(e1.w);
        w[4] = __int_as_float(e2.y); w[5] = __int_as_float(e2.w);
        w[6] = __int_as_float(e3.y); w[7] = __int_as_float(e3.w);
#pragma unroll
        for (int i = 0; i < 8; i++)
#pragma unroll
            for (int k = 0; k < 4; k++) acc[k] = fmaf(w[i], f[i][k], acc[k]);
    }
    if (j < endp) {
        int4 e0 = *(const int4*)(csr + j);
        int4 e1 = *(const int4*)(csr + j + 2);
        float f[4][4];
        ldrow_h4(f[0], h + e0.x * 84 + off);
        ldrow_h4(f[1], h + e0.z * 84 + off);
        ldrow_h4(f[2], h + e1.x * 84 + off);
        ldrow_h4(f[3], h + e1.z * 84 + off);
        float w[4];
        w[0] = __int_as_float(e0.y); w[1] = __int_as_float(e0.w);
        w[2] = __int_as_float(e1.y); w[3] = __int_as_float(e1.w);
#pragma unroll
        for (int i = 0; i < 4; i++)
#pragma unroll
            for (int k = 0; k < 4; k++) acc[k] = fmaf(w[i], f[i][k], acc[k]);
    }

    float s2 = dv * dv;
    float* po = out + v * 84 + off;
#pragma unroll
    for (int k = 0; k < 4; k++) {
        float r2 = fmaf(s2, pvv[k], acc[k]);
        r2 = fmaxf(r2 + bias[off + k], 0.f);
        po[k] = r2;
    }
}

// ---------------- scalar GEMM (layer 4 — exact fp32) ----------------

#define GBM 256
#define GBN 32
#define GBK 16

__global__ void __launch_bounds__(256)
k_gemm(const float* __restrict__ A, const float* __restrict__ W,
       const float* __restrict__ bias, float* __restrict__ Cout,
       int N, int K, int M, int SA, int SC, int fuse_bias_relu) {
    __shared__ float As[GBK][GBM];
    __shared__ float Bs[GBK][GBN];

    int tid = threadIdx.x;
    int bm = blockIdx.x * GBM;
    int bn = blockIdx.y * GBN;
    int ty = tid >> 3;
    int tx = tid & 7;
    int row0 = ty * 8;
    int col0 = tx * 4;

    float acc[8][4];
#pragma unroll
    for (int i = 0; i < 8; i++)
#pragma unroll
        for (int j = 0; j < 4; j++) acc[i][j] = 0.f;

    for (int k0 = 0; k0 < K; k0 += GBK) {
#pragma unroll
        for (int i = 0; i < 4; i++) {
            int lin4 = tid + i * 256;
            int r = lin4 >> 2;
            int kk4 = lin4 & 3;
            int gr = bm + r;
            int gk0 = k0 + kk4 * 4;
            float4 a = make_float4(0.f, 0.f, 0.f, 0.f);
            if (gr < N && gk0 + 3 < SA)
                a = *(const float4*)(A + (size_t)gr * SA + gk0);
            As[kk4 * 4 + 0][r] = a.x;
            As[kk4 * 4 + 1][r] = a.y;
            As[kk4 * 4 + 2][r] = a.z;
            As[kk4 * 4 + 3][r] = a.w;
        }
#pragma unroll
        for (int i = 0; i < 2; i++) {
            int lin = tid + i * 256;
            int r = lin >> 5;
            int c = lin & 31;
            int gk = k0 + r, gc = bn + c;
            Bs[r][c] = (gk < K && gc < M) ? W[(size_t)gk * M + gc] : 0.f;
        }
        __syncthreads();

#pragma unroll
        for (int kk = 0; kk < GBK; kk++) {
            float4 a0 = *(const float4*)&As[kk][row0];
            float4 a1 = *(const float4*)&As[kk][row0 + 4];
            float4 b  = *(const float4*)&Bs[kk][col0];
            float av[8] = {a0.x, a0.y, a0.z, a0.w, a1.x, a1.y, a1.z, a1.w};
            float bv[4] = {b.x, b.y, b.z, b.w};
#pragma unroll
            for (int i = 0; i < 8; i++)
#pragma unroll
                for (int j = 0; j < 4; j++) acc[i][j] = fmaf(av[i], bv[j], acc[i][j]);
        }
        __syncthreads();
    }

#pragma unroll
    for (int i = 0; i < 8; i++) {
        int gr = bm + row0 + i;
        if (gr < N) {
#pragma unroll
            for (int j = 0; j < 4; j++) {
                int gc = bn + col0 + j;
                if (gc < M) {
                    float v = acc[i][j];
                    if (fuse_bias_relu) v = fmaxf(v + bias[gc], 0.f);
                    Cout[(size_t)gr * SC + gc] = v;
                }
            }
        }
    }
}

// ---------------- tf32 tensor-core GEMM (layers 1, 2, 3) ----------------
// C[N x M] = A[N x K] @ W[K x M]; mma.m16n8k8.tf32, fp32 accumulate.
// Optional fused bias+relu; optional fp16 output (CoutH != null).

__device__ __forceinline__ uint32_t f2tf32(float x) {
    uint32_t r;
    asm("cvt.rna.tf32.f32 %0, %1;" : "=r"(r) : "f"(x));
    return r;
}

#define TAS 132   // padded smem row stride (conflict-free frag reads)

__global__ void __launch_bounds__(128)
k_gemm_tc(const float* __restrict__ A, const float* __restrict__ W,
          const float* __restrict__ bias, float* __restrict__ Cout,
          __half* __restrict__ CoutH,
          int N, int K, int M, int SA, int SC, int fuse_bias_relu) {
    __shared__ float As[8][TAS];          // [k][row], tf32-converted

    int tid = threadIdx.x;
    int warp = tid >> 5;
    int lane = tid & 31;
    int g  = lane >> 2;
    int tg = lane & 3;
    int bm = blockIdx.x * 128;
    int bn = blockIdx.y * 32;
    int wr = warp * 32;

    float c[2][4][4];
#pragma unroll
    for (int mt = 0; mt < 2; mt++)
#pragma unroll
        for (int t = 0; t < 4; t++)
#pragma unroll
            for (int q = 0; q < 4; q++) c[mt][t][q] = 0.f;

    int ksteps = (K + 7) >> 3;
    for (int ks = 0; ks < ksteps; ks++) {
        int k0 = ks << 3;
        {
            int gr = bm + tid;
            float4 a0 = make_float4(0.f, 0.f, 0.f, 0.f);
            float4 a1 = a0;
            if (gr < N) {
                const float* p = A + (size_t)gr * SA + k0;
                a0 = *(const float4*)p;
                a1 = *(const float4*)(p + 4);
            }
            As[0][tid] = __uint_as_float(f2tf32(a0.x));
            As[1][tid] = __uint_as_float(f2tf32(a0.y));
            As[2][tid] = __uint_as_float(f2tf32(a0.z));
            As[3][tid] = __uint_as_float(f2tf32(a0.w));
            As[4][tid] = __uint_as_float(f2tf32(a1.x));
            As[5][tid] = __uint_as_float(f2tf32(a1.y));
            As[6][tid] = __uint_as_float(f2tf32(a1.z));
            As[7][tid] = __uint_as_float(f2tf32(a1.w));
        }
        __syncthreads();

        uint32_t bfr[4][2];
#pragma unroll
        for (int t = 0; t < 4; t++) {
            int col = bn + t * 8 + g;
            int r0 = k0 + tg;
            int r1 = r0 + 4;
            float b0 = (r0 < K && col < M) ? W[(size_t)r0 * M + col] : 0.f;
            float b1 = (r1 < K && col < M) ? W[(size_t)r1 * M + col] : 0.f;
            bfr[t][0] = f2tf32(b0);
            bfr[t][1] = f2tf32(b1);
        }

#pragma unroll
        for (int mt = 0; mt < 2; mt++) {
            int r = wr + mt * 16 + g;
            uint32_t a0 = __float_as_uint(As[tg][r]);
            uint32_t a1 = __float_as_uint(As[tg][r + 8]);
            uint32_t a2 = __float_as_uint(As[tg + 4][r]);
            uint32_t a3 = __float_as_uint(As[tg + 4][r + 8]);
#pragma unroll
            for (int t = 0; t < 4; t++) {
                asm volatile(
                    "mma.sync.aligned.m16n8k8.row.col.f32.tf32.tf32.f32 "
                    "{%0,%1,%2,%3}, {%4,%5,%6,%7}, {%8,%9}, {%0,%1,%2,%3};"
                    : "+f"(c[mt][t][0]), "+f"(c[mt][t][1]),
                      "+f"(c[mt][t][2]), "+f"(c[mt][t][3])
                    : "r"(a0), "r"(a1), "r"(a2), "r"(a3),
                      "r"(bfr[t][0]), "r"(bfr[t][1]));
            }
        }
        __syncthreads();
    }

#pragma unroll
    for (int mt = 0; mt < 2; mt++) {
#pragma unroll
        for (int t = 0; t < 4; t++) {
            int col = bn + t * 8 + 2 * tg;
            int r0 = bm + wr + mt * 16 + g;
            float v0 = c[mt][t][0], v1 = c[mt][t][1];
            float v2 = c[mt][t][2], v3 = c[mt][t][3];
            if (fuse_bias_relu) {
                if (col < M) {
                    float bb0 = bias[col];
                    v0 = fmaxf(v0 + bb0, 0.f);
                    v2 = fmaxf(v2 + bb0, 0.f);
                }
                if (col + 1 < M) {
                    float bb1 = bias[col + 1];
                    v1 = fmaxf(v1 + bb1, 0.f);
                    v3 = fmaxf(v3 + bb1, 0.f);
                }
            }
            if (CoutH) {
                if (col + 1 < M) {
                    if (r0 < N)
                        *(__half2*)(CoutH + (size_t)r0 * SC + col) =
                            __floats2half2_rn(v0, v1);
                    if (r0 + 8 < N)
                        *(__half2*)(CoutH + (size_t)(r0 + 8) * SC + col) =
                            __floats2half2_rn(v2, v3);
                } else if (col < M) {
                    if (r0 < N) CoutH[(size_t)r0 * SC + col] = __float2half_rn(v0);
                    if (r0 + 8 < N) CoutH[(size_t)(r0 + 8) * SC + col] = __float2half_rn(v2);
                }
            } else {
                if (col + 1 < M) {
                    if (r0 < N)
                        *(float2*)(Cout + (size_t)r0 * SC + col) = make_float2(v0, v1);
                    if (r0 + 8 < N)
                        *(float2*)(Cout + (size_t)(r0 + 8) * SC + col) = make_float2(v2, v3);
                } else if (col < M) {
                    if (r0 < N) Cout[(size_t)r0 * SC + col] = v0;
                    if (r0 + 8 < N) Cout[(size_t)(r0 + 8) * SC + col] = v2;
                }
            }
        }
    }
}

// ---------------- final: CSR agg + bias + relu + log_softmax (warp/node) --------

__global__ void k_final(const float* __restrict__ t4,       // stride 24
                        const int* __restrict__ row_beg,
                        const int* __restrict__ ideg,
                        const Edge* __restrict__ csr,
                        const float* __restrict__ dinv,
                        const float* __restrict__ b4,
                        float* __restrict__ out_z, float* __restrict__ out_pz, int n) {
    int v = (blockIdx.x * blockDim.x + threadIdx.x) >> 5;
    int lane = threadIdx.x & 31;
    if (v >= n) return;

    float val = -INFINITY;
    if (lane < 21) {
        int beg = row_beg[v];
        int endp = beg + ((ideg[v] + 3) & ~3);
        float dv = dinv[v];
        float selfv = t4[v * 24 + lane];
        float acc = 0.f;

        int j = beg;
        for (; j + 8 <= endp; j += 8) {
            int4 e0 = *(const int4*)(csr + j);
            int4 e1 = *(const int4*)(csr + j + 2);
            int4 e2 = *(const int4*)(csr + j + 4);
            int4 e3 = *(const int4*)(csr + j + 6);
            float f0 = t4[e0.x * 24 + lane];
            float f1 = t4[e0.z * 24 + lane];
            float f2 = t4[e1.x * 24 + lane];
            float f3 = t4[e1.z * 24 + lane];
            float f4 = t4[e2.x * 24 + lane];
            float f5 = t4[e2.z * 24 + lane];
            float f6 = t4[e3.x * 24 + lane];
            float f7 = t4[e3.z * 24 + lane];
            acc = fmaf(__int_as_float(e0.y), f0, acc);
            acc = fmaf(__int_as_float(e0.w), f1, acc);
            acc = fmaf(__int_as_float(e1.y), f2, acc);
            acc = fmaf(__int_as_float(e1.w), f3, acc);
            acc = fmaf(__int_as_float(e2.y), f4, acc);
            acc = fmaf(__int_as_float(e2.w), f5, acc);
            acc = fmaf(__int_as_float(e3.y), f6, acc);
            acc = fmaf(__int_as_float(e3.w), f7, acc);
        }
        if (j < endp) {
            int4 e0 = *(const int4*)(csr + j);
            int4 e1 = *(const int4*)(csr + j + 2);
            float f0 = t4[e0.x * 24 + lane];
            float f1 = t4[e0.z * 24 + lane];
            float f2 = t4[e1.x * 24 + lane];
            float f3 = t4[e1.z * 24 + lane];
            acc = fmaf(__int_as_float(e0.y), f0, acc);
            acc = fmaf(__int_as_float(e0.w), f1, acc);
            acc = fmaf(__int_as_float(e1.y), f2, acc);
            acc = fmaf(__int_as_float(e1.w), f3, acc);
        }
        acc = fmaf(dv * dv, selfv, acc);
        val = fmaxf(acc + b4[lane], 0.f);
    }

    float m = val;
#pragma unroll
    for (int o = 16; o > 0; o >>= 1) m = fmaxf(m, __shfl_xor_sync(0xffffffffu, m, o));
    float ex = (lane < 21) ? __expf(val - m) : 0.f;
    float s = ex;
#pragma unroll
    for (int o = 16; o > 0; o >>= 1) s += __shfl_xor_sync(0xffffffffu, s, o);

    if (lane < 21) {
        out_z[v * 21 + lane] = val;
        out_pz[v * 21 + lane] = val - m - __logf(s);
    }
}

// ---------------------------------------------------------------------------

static inline int cdiv(long long a, int b) { return (int)((a + b - 1) / b); }

extern "C" void kernel_launch(void* const* d_in, const int* in_sizes, int n_in,
                              void* d_out, int out_size) {
    const float* x  = (const float*)d_in[0];
    const int*   ei = (const int*)d_in[1];
    const float* W1 = (const float*)d_in[2];  const float* b1 = (const float*)d_in[3];
    const float* W2 = (const float*)d_in[4];  const float* b2 = (const float*)d_in[5];
    const float* W3 = (const float*)d_in[6];  const float* b3 = (const float*)d_in[7];
    const float* W4 = (const float*)d_in[8];  const float* b4 = (const float*)d_in[9];

    const int n = in_sizes[0] / 21;
    const int E = in_sizes[1] / 2;

    float *bufA, *bufB, *dinv;
    __half* bufH;
    int *ideg, *row_beg, *cur, *counter;
    Edge* csr;
    cudaGetSymbolAddress((void**)&bufA, g_bufA);
    cudaGetSymbolAddress((void**)&bufB, g_bufB);
    cudaGetSymbolAddress((void**)&bufH, g_bufH);
    cudaGetSymbolAddress((void**)&dinv, g_dinv);
    cudaGetSymbolAddress((void**)&ideg, g_ideg);
    cudaGetSymbolAddress((void**)&row_beg, g_rowbeg);
    cudaGetSymbolAddress((void**)&cur, g_cur);
    cudaGetSymbolAddress((void**)&counter, g_counter);
    cudaGetSymbolAddress((void**)&csr, g_csr);

    float* out_pz = (float*)d_out;
    float* out_z  = (float*)d_out + (size_t)n * 21;

    const int T = 256;
    const int nb = cdiv(n, SCAN_B);

    // --- CSR build (4 launches) ---
    k_init<<<cdiv(n, T), T>>>(ideg, cur, counter, n);
    k_count_deg<<<cdiv(E, T), T>>>(ei, ideg, E);
    k_offsets<<<nb, SCAN_B>>>(ideg, row_beg, dinv, csr, counter, n);
    k_scatter<<<cdiv(E, T), T>>>(ei, row_beg, cur, dinv, csr, E);

    // --- layer 1: dense agg of x (C=21, TPN=24), TC GEMM 21->168 (+bias+relu) ---
    k_agg<21, 1, 21, 24><<<cdiv((long long)n * 24, T), T>>>(
        x, row_beg, ideg, csr, dinv, nullptr, bufA, n);
    {
        dim3 grid(cdiv(n, 128), cdiv(168, 32));
        k_gemm_tc<<<grid, 128>>>(bufA, W1, b1, bufB, nullptr, n, 21, 168, 24, 168, 1);
    }
    // --- layer 2: TC GEMM 168->84 (fp16 out), fp16 agg+bias+relu (C=84, VW=4) ---
    {
        dim3 grid(cdiv(n, 128), cdiv(84, 32));
        k_gemm_tc<<<grid, 128>>>(bufB, W2, nullptr, nullptr, bufH, n, 168, 84, 168, 84, 0);
    }
    k_agg_h<<<cdiv((long long)n * 21, T), T>>>(
        bufH, row_beg, ideg, csr, dinv, b2, bufB, n);
    // --- layer 3: TC GEMM 84->42 (out stride 44), dense agg (C=42, VW=2) ---
    {
        dim3 grid(cdiv(n, 128), cdiv(42, 32));
        k_gemm_tc<<<grid, 128>>>(bufB, W3, nullptr, bufA, nullptr, n, 84, 42, 84, 44, 0);
    }
    k_agg<42, 2, 44, 44><<<cdiv((long long)n * 22, T), T>>>(
        bufA, row_beg, ideg, csr, dinv, b3, bufB, n);
    // --- layer 4: scalar GEMM 42->21 (out stride 24), fused final ---
    {
        dim3 grid(cdiv(n, GBM), cdiv(21, GBN));
        k_gemm<<<grid, T>>>(bufB, W4, nullptr, bufA, n, 42, 21, 44, 24, 0);
    }
    k_final<<<cdiv((long long)n * 32, T), T>>>(
        bufA, row_beg, ideg, csr, dinv, b4, out_z, out_pz, n);
}